// round 8
// baseline (speedup 1.0000x reference)
#include <cuda_runtime.h>
#include <cuda_bf16.h>
#include <cstdint>

#define NN   22528
#define EE   360448
#define FEA  60
#define HID  512
#define OUTD 4
#define MA   22
#define BGR  1024
#define CAT  572
#define FLAT 12584
#define KP0  12608
#define NCH0 197

// ---------------- device scratch ----------------
__device__ int   g_flag;
__device__ float g_deg[NN];
__device__ float g_dis[NN];
__device__ int   g_row[EE];
__device__ int   g_col[EE];
__device__ int   g_cnt[NN];
__device__ int   g_cur[NN];
__device__ int   g_off[NN + 1];
__device__ int   g_src[EE];
__device__ float g_w[EE];
__device__ int   g_tilecnt[32];

__device__ __align__(16) __nv_bfloat16 g_aggx_h[(size_t)NN * 64];
__device__ __align__(16) __nv_bfloat16 g_aggx_l[(size_t)NN * 64];
__device__ __align__(16) __nv_bfloat16 g_W1t_h[512 * 64];
__device__ __align__(16) __nv_bfloat16 g_W1t_l[512 * 64];
__device__ __align__(16) float         g_h1[(size_t)NN * HID];
__device__ __align__(16) __nv_bfloat16 g_W2t_h[512 * 512];
__device__ __align__(16) __nv_bfloat16 g_W2t_l[512 * 512];
__device__ __align__(16) __nv_bfloat16 g_agg1_h[(size_t)NN * HID];
__device__ __align__(16) __nv_bfloat16 g_agg1_l[(size_t)NN * HID];
__device__ __align__(16) __nv_bfloat16 g_xcat_h[(size_t)BGR * KP0];
__device__ __align__(16) __nv_bfloat16 g_xcat_l[(size_t)BGR * KP0];
__device__ __align__(16) __nv_bfloat16 g_Wf0t_h[(size_t)512 * KP0];
__device__ __align__(16) __nv_bfloat16 g_Wf0t_l[(size_t)512 * KP0];
__device__ __align__(16) float         g_t0f[BGR * HID];
__device__ __align__(16) __nv_bfloat16 g_t0_h[BGR * HID];
__device__ __align__(16) __nv_bfloat16 g_t0_l[BGR * HID];
__device__ __align__(16) __nv_bfloat16 g_Wf1t_h[512 * 512];
__device__ __align__(16) __nv_bfloat16 g_Wf1t_l[512 * 512];
__device__ __align__(16) __nv_bfloat16 g_t1_h[BGR * HID];
__device__ __align__(16) __nv_bfloat16 g_t1_l[BGR * HID];
__device__ __align__(16) __nv_bfloat16 g_Wf2t_h[512 * 512];
__device__ __align__(16) __nv_bfloat16 g_Wf2t_l[512 * 512];
__device__ __align__(16) float         g_t2[BGR * HID];

// ---------------- helpers ----------------
__device__ __forceinline__ uint32_t smem_u32(const void* p) {
    uint32_t a;
    asm("{ .reg .u64 t; cvta.to.shared.u64 t, %1; cvt.u32.u64 %0, t; }" : "=r"(a) : "l"(p));
    return a;
}
__device__ __forceinline__ void ldsm4(uint32_t* r, uint32_t addr) {
    asm volatile("ldmatrix.sync.aligned.m8n8.x4.shared.b16 {%0,%1,%2,%3}, [%4];"
        : "=r"(r[0]), "=r"(r[1]), "=r"(r[2]), "=r"(r[3]) : "r"(addr));
}
__device__ __forceinline__ void mma16816(float* d, const uint32_t* a, uint32_t b0, uint32_t b1) {
    asm volatile("mma.sync.aligned.m16n8k16.row.col.f32.bf16.bf16.f32 "
        "{%0,%1,%2,%3}, {%4,%5,%6,%7}, {%8,%9}, {%0,%1,%2,%3};"
        : "+f"(d[0]), "+f"(d[1]), "+f"(d[2]), "+f"(d[3])
        : "r"(a[0]), "r"(a[1]), "r"(a[2]), "r"(a[3]), "r"(b0), "r"(b1));
}
#define CP16(d, s)   asm volatile("cp.async.cg.shared.global [%0], [%1], 16;" :: "r"(d), "l"(s))
#define CP_COMMIT()  asm volatile("cp.async.commit_group;" ::: "memory")
#define CP_WAIT0()   asm volatile("cp.async.wait_group 0;" ::: "memory")
#define CP_WAIT1()   asm volatile("cp.async.wait_group 1;" ::: "memory")

__device__ __forceinline__ float lrelu(float v) { return v > 0.f ? v : 0.01f * v; }
__device__ __forceinline__ void split_bf16(float v, __nv_bfloat16& h, __nv_bfloat16& l) {
    h = __float2bfloat16(v);
    l = __float2bfloat16(v - __bfloat162float(h));
}

// ---------------- setup ----------------
__global__ void k_setup(const int* ei) {
    int i = blockIdx.x * blockDim.x + threadIdx.x;
    if (i < NN) { g_deg[i] = 1.0f; g_cnt[i] = 0; g_cur[i] = 0; }
    if (i < 32) g_tilecnt[i] = 0;
    if (i == 0) {
        int f = 1;
        for (int j = 0; j < 64; j++)
            if (ei[2 * j + 1] != 0) { f = 0; break; }
        g_flag = f;
    }
}
__global__ void k_edges(const void* ei, const float* __restrict__ ew) {
    int e = blockIdx.x * blockDim.x + threadIdx.x;
    if (e >= EE) return;
    int r, c;
    if (g_flag) {
        const long long* p = (const long long*)ei;
        r = (int)p[e]; c = (int)p[EE + e];
    } else {
        const int* p = (const int*)ei;
        r = p[e]; c = p[EE + e];
    }
    g_row[e] = r; g_col[e] = c;
    atomicAdd(&g_deg[c], ew[e]);
    atomicAdd(&g_cnt[c], 1);
}
__global__ void k_scan_dis() {
    __shared__ int sh[1024];
    int t = threadIdx.x;
    int base = t * 22;
    int local[22];
    int s = 0;
    #pragma unroll
    for (int i = 0; i < 22; i++) {
        local[i] = g_cnt[base + i];
        s += local[i];
        float d = g_deg[base + i];
        g_dis[base + i] = (d > 0.f) ? rsqrtf(d) : 0.f;
    }
    sh[t] = s;
    __syncthreads();
    for (int off = 1; off < 1024; off <<= 1) {
        int v = (t >= off) ? sh[t - off] : 0;
        __syncthreads();
        sh[t] += v;
        __syncthreads();
    }
    int pre = (t == 0) ? 0 : sh[t - 1];
    #pragma unroll
    for (int i = 0; i < 22; i++) { g_off[base + i] = pre; pre += local[i]; }
    if (t == 0) g_off[NN] = EE;
}
__global__ void k_fill(const float* __restrict__ ew) {
    int e = blockIdx.x * blockDim.x + threadIdx.x;
    if (e >= EE) return;
    int r = g_row[e], c = g_col[e];
    int p = g_off[c] + atomicAdd(&g_cur[c], 1);
    g_src[p] = r;
    g_w[p] = g_dis[r] * ew[e] * g_dis[c];
}

// ---------------- CSR gathers (2-way unrolled) ----------------
__global__ void k_gather1(const float* __restrict__ x) {
    int n = blockIdx.x;
    int f = threadIdx.x;               // 64
    float d = g_dis[n];
    float acc = 0.f;
    if (f < FEA) acc = d * d * x[(size_t)n * FEA + f];
    int s = g_off[n], e = g_off[n + 1];
    int p = s;
    for (; p + 1 < e; p += 2) {
        int s0 = g_src[p], s1 = g_src[p + 1];
        float w0 = g_w[p], w1 = g_w[p + 1];
        if (f < FEA) {
            float v0 = x[(size_t)s0 * FEA + f];
            float v1 = x[(size_t)s1 * FEA + f];
            acc += v0 * w0 + v1 * w1;
        }
    }
    if (p < e && f < FEA) acc += x[(size_t)g_src[p] * FEA + f] * g_w[p];
    if (f >= FEA) acc = 0.f;
    __nv_bfloat16 h, l;
    split_bf16(acc, h, l);
    g_aggx_h[(size_t)n * 64 + f] = h;
    g_aggx_l[(size_t)n * 64 + f] = l;
}

__global__ void k_gather2() {
    int n = blockIdx.x;
    int f4 = threadIdx.x;              // 128 threads, float4 each
    float d = g_dis[n];
    float s2 = d * d;
    float4 acc = ((const float4*)(g_h1 + (size_t)n * HID))[f4];
    acc.x *= s2; acc.y *= s2; acc.z *= s2; acc.w *= s2;
    int s = g_off[n], e = g_off[n + 1];
    int p = s;
    for (; p + 1 < e; p += 2) {
        int s0 = g_src[p], s1 = g_src[p + 1];
        float w0 = g_w[p], w1 = g_w[p + 1];
        float4 v0 = ((const float4*)(g_h1 + (size_t)s0 * HID))[f4];
        float4 v1 = ((const float4*)(g_h1 + (size_t)s1 * HID))[f4];
        acc.x += v0.x * w0 + v1.x * w1;
        acc.y += v0.y * w0 + v1.y * w1;
        acc.z += v0.z * w0 + v1.z * w1;
        acc.w += v0.w * w0 + v1.w * w1;
    }
    if (p < e) {
        float w = g_w[p];
        float4 v = ((const float4*)(g_h1 + (size_t)g_src[p] * HID))[f4];
        acc.x += v.x * w; acc.y += v.y * w;
        acc.z += v.z * w; acc.w += v.w * w;
    }
    __nv_bfloat16 h0, l0, h1b, l1, h2, l2, h3, l3;
    split_bf16(acc.x, h0, l0);
    split_bf16(acc.y, h1b, l1);
    split_bf16(acc.z, h2, l2);
    split_bf16(acc.w, h3, l3);
    size_t o = (size_t)n * HID + f4 * 4;
    *(__nv_bfloat162*)&g_agg1_h[o]     = __nv_bfloat162(h0, h1b);
    *(__nv_bfloat162*)&g_agg1_h[o + 2] = __nv_bfloat162(h2, h3);
    *(__nv_bfloat162*)&g_agg1_l[o]     = __nv_bfloat162(l0, l1);
    *(__nv_bfloat162*)&g_agg1_l[o + 2] = __nv_bfloat162(l2, l3);
}

// ---------------- all weight transposes, one kernel ----------------
// flat block id: [0,32) W1 | [32,800) W2/Wf1/Wf2 | [800,7104) Wf0
__global__ void k_wall(const float* __restrict__ W1, const float* __restrict__ W2,
                       const float* __restrict__ Wf1, const float* __restrict__ Wf2,
                       const float* __restrict__ Wf0) {
    __shared__ float tile[32][33];
    int b = blockIdx.x;
    const float* W;
    __nv_bfloat16 *oh, *ol;
    int K, Kpad, gx, r;
    if (b < 32) {
        W = W1; oh = g_W1t_h; ol = g_W1t_l; K = FEA; Kpad = 64; gx = 2; r = b;
    } else if (b < 800) {
        int z = (b - 32) >> 8;
        r = (b - 32) & 255;
        W = (z == 0) ? W2 : (z == 1) ? Wf1 : Wf2;
        oh = (z == 0) ? g_W2t_h : (z == 1) ? g_Wf1t_h : g_Wf2t_h;
        ol = (z == 0) ? g_W2t_l : (z == 1) ? g_Wf1t_l : g_Wf2t_l;
        K = 512; Kpad = 512; gx = 16;
    } else {
        W = Wf0; oh = g_Wf0t_h; ol = g_Wf0t_l; K = FLAT; Kpad = KP0; gx = KP0 / 32; r = b - 800;
    }
    int kb = (r % gx) * 32, nb = (r / gx) * 32;
    int tx = threadIdx.x, ty = threadIdx.y;   // 32 x 8
    #pragma unroll
    for (int i = 0; i < 4; i++) {
        int row = kb + ty + i * 8;
        tile[ty + i * 8][tx] = (row < K) ? W[(size_t)row * 512 + nb + tx] : 0.f;
    }
    __syncthreads();
    #pragma unroll
    for (int i = 0; i < 4; i++) {
        int n = nb + ty + i * 8;
        int k = kb + tx;
        float v = tile[tx][ty + i * 8];
        __nv_bfloat16 h, l;
        split_bf16(v, h, l);
        oh[(size_t)n * Kpad + k] = h;
        ol[(size_t)n * Kpad + k] = l;
    }
}

// copyx + pad + zero t0f, one kernel
__global__ void k_copyx(const float* __restrict__ x) {
    int t = blockIdx.x * blockDim.x + threadIdx.x;
    if (t < NN * FEA) {
        int n = t / FEA, f = t - n * FEA;
        int b = n / MA, j = n - b * MA;
        size_t o = (size_t)b * KP0 + j * CAT + HID + f;
        __nv_bfloat16 h, l;
        split_bf16(x[t], h, l);
        g_xcat_h[o] = h;
        g_xcat_l[o] = l;
    } else if (t < NN * FEA + BGR * 24) {
        int t2 = t - NN * FEA;
        int b = t2 / 24, f = t2 - b * 24;
        size_t o = (size_t)b * KP0 + FLAT + f;
        g_xcat_h[o] = __float2bfloat16(0.f);
        g_xcat_l[o] = __float2bfloat16(0.f);
    } else if (t < NN * FEA + BGR * 24 + BGR * HID) {
        g_t0f[t - NN * FEA - BGR * 24] = 0.f;
    }
}

// ================= 128x128 mma GEMM, 3-stage cp.async =================
// EPI: 0 fp32+bias+lrelu, 2 xcat-scatter bf16 hi/lo, 3 split-K atomic + last-CTA
// finalize (bias+lrelu+split into Ch/Cl).
#define OFF_AL 18432u
#define OFF_BH 36864u
#define OFF_BL 55296u
#define BUFSZ  73728u

template <int EPI>
__global__ void __launch_bounds__(256, 1)
k_mma_gemm(const __nv_bfloat16* __restrict__ Ah, const __nv_bfloat16* __restrict__ Al, int lda,
           const __nv_bfloat16* __restrict__ Bh, const __nv_bfloat16* __restrict__ Bl, int ldb,
           const float* __restrict__ bias,
           float* __restrict__ Cf, __nv_bfloat16* __restrict__ Ch, __nv_bfloat16* __restrict__ Cl,
           int ldc, int nch, int cper)
{
    extern __shared__ char smx[];
    const uint32_t smb = smem_u32(smx);
    const int tid = threadIdx.x;
    const int wid = tid >> 5, lane = tid & 31;
    const int wm = wid & 1, wn = wid >> 1;
    const int row0 = blockIdx.y * 128, col0 = blockIdx.x * 128;
    const int c0 = blockIdx.z * cper;
    const int nc = min(nch, c0 + cper) - c0;

    const __nv_bfloat16* pAh = Ah + (size_t)row0 * lda;
    const __nv_bfloat16* pAl = Al + (size_t)row0 * lda;
    const __nv_bfloat16* pBh = Bh + (size_t)col0 * ldb;
    const __nv_bfloat16* pBl = Bl + (size_t)col0 * ldb;

    auto fill = [&](int b, int c) {
        const int kb = c * 64;
        uint32_t base = smb + b * BUFSZ;
        #pragma unroll
        for (int i = 0; i < 4; i++) {
            int idx = i * 256 + tid;
            int row = idx >> 3, seg = idx & 7;
            uint32_t d = base + (uint32_t)(row * 144 + seg * 16);
            size_t sa = (size_t)row * lda + kb + seg * 8;
            size_t sb = (size_t)row * ldb + kb + seg * 8;
            CP16(d,          pAh + sa);
            CP16(d + OFF_AL, pAl + sa);
            CP16(d + OFF_BH, pBh + sb);
            CP16(d + OFF_BL, pBl + sb);
        }
    };

    float acc[4][4][4];
    #pragma unroll
    for (int i = 0; i < 4; i++)
        #pragma unroll
        for (int j = 0; j < 4; j++)
            #pragma unroll
            for (int q = 0; q < 4; q++) acc[i][j][q] = 0.f;

    const int g2 = lane >> 3, rr = lane & 7;
    const uint32_t aoff = (uint32_t)((wm * 64 + (g2 & 1) * 8 + rr) * 144 + (g2 >> 1) * 16);
    const uint32_t boff = (uint32_t)((wn * 32 + (g2 >> 1) * 8 + rr) * 144 + (g2 & 1) * 16);

    fill(0, c0);
    CP_COMMIT();
    if (nc > 1) { fill(1, c0 + 1); CP_COMMIT(); }

    for (int ci = 0; ci < nc; ci++) {
        if (ci + 1 < nc) CP_WAIT1(); else CP_WAIT0();
        __syncthreads();
        if (ci + 2 < nc) { fill((ci + 2) % 3, c0 + ci + 2); CP_COMMIT(); }
        uint32_t base = smb + (uint32_t)(ci % 3) * BUFSZ;
        #pragma unroll
        for (int k16 = 0; k16 < 4; k16++) {
            uint32_t Af[4][4], Lf[4][4], Bf[2][4], Mf[2][4];
            #pragma unroll
            for (int mt = 0; mt < 4; mt++) {
                ldsm4(Af[mt], base + aoff + mt * 2304 + k16 * 32);
                ldsm4(Lf[mt], base + OFF_AL + aoff + mt * 2304 + k16 * 32);
            }
            #pragma unroll
            for (int nt2 = 0; nt2 < 2; nt2++) {
                ldsm4(Bf[nt2], base + OFF_BH + boff + nt2 * 2304 + k16 * 32);
                ldsm4(Mf[nt2], base + OFF_BL + boff + nt2 * 2304 + k16 * 32);
            }
            #pragma unroll
            for (int mt = 0; mt < 4; mt++)
                #pragma unroll
                for (int nt = 0; nt < 4; nt++) {
                    uint32_t bh0 = Bf[nt >> 1][(nt & 1) * 2], bh1 = Bf[nt >> 1][(nt & 1) * 2 + 1];
                    uint32_t bl0 = Mf[nt >> 1][(nt & 1) * 2], bl1 = Mf[nt >> 1][(nt & 1) * 2 + 1];
                    mma16816(acc[mt][nt], Af[mt], bh0, bh1);
                    mma16816(acc[mt][nt], Af[mt], bl0, bl1);
                    mma16816(acc[mt][nt], Lf[mt], bh0, bh1);
                }
        }
        __syncthreads();
    }

    const int g = lane >> 2, t = lane & 3;
    #pragma unroll
    for (int mt = 0; mt < 4; mt++) {
        const int ra = row0 + wm * 64 + mt * 16 + g;
        const int rb = ra + 8;
        size_t oa = 0, ob = 0;
        if (EPI == 2) {
            int bg = ra / MA, j = ra - bg * MA;
            oa = (size_t)bg * KP0 + (size_t)j * CAT;
            bg = rb / MA; j = rb - bg * MA;
            ob = (size_t)bg * KP0 + (size_t)j * CAT;
        }
        #pragma unroll
        for (int nt = 0; nt < 4; nt++) {
            const int c = col0 + wn * 32 + nt * 8 + t * 2;
            float* d = acc[mt][nt];
            if (EPI == 3) {
                atomicAdd(&Cf[(size_t)ra * ldc + c],     d[0]);
                atomicAdd(&Cf[(size_t)ra * ldc + c + 1], d[1]);
                atomicAdd(&Cf[(size_t)rb * ldc + c],     d[2]);
                atomicAdd(&Cf[(size_t)rb * ldc + c + 1], d[3]);
            } else {
                float2 bv = *(const float2*)&bias[c];
                float v00 = lrelu(d[0] + bv.x), v01 = lrelu(d[1] + bv.y);
                float v10 = lrelu(d[2] + bv.x), v11 = lrelu(d[3] + bv.y);
                if (EPI == 0) {
                    float2 oA = {v00, v01}, oB = {v10, v11};
                    *(float2*)&Cf[(size_t)ra * ldc + c] = oA;
                    *(float2*)&Cf[(size_t)rb * ldc + c] = oB;
                } else {
                    __nv_bfloat16 h00, l00, h01, l01, h10, l10, h11, l11;
                    split_bf16(v00, h00, l00);
                    split_bf16(v01, h01, l01);
                    split_bf16(v10, h10, l10);
                    split_bf16(v11, h11, l11);
                    *(__nv_bfloat162*)&Ch[oa + c] = __nv_bfloat162(h00, h01);
                    *(__nv_bfloat162*)&Cl[oa + c] = __nv_bfloat162(l00, l01);
                    *(__nv_bfloat162*)&Ch[ob + c] = __nv_bfloat162(h10, h11);
                    *(__nv_bfloat162*)&Cl[ob + c] = __nv_bfloat162(l10, l11);
                }
            }
        }
    }

    // split-K finalize: last z-CTA of this (x,y) tile applies bias+lrelu+split
    if (EPI == 3) {
        __shared__ int slast;
        __threadfence();
        __syncthreads();
        if (tid == 0) {
            int tl = blockIdx.y * gridDim.x + blockIdx.x;
            slast = (atomicAdd(&g_tilecnt[tl], 1) == (int)gridDim.z - 1) ? 1 : 0;
        }
        __syncthreads();
        if (slast) {
            for (int i = tid; i < 128 * 32; i += 256) {   // 128 rows x 32 float4
                int r = row0 + (i >> 5);
                int c = col0 + (i & 31) * 4;
                float4 v = *(const float4*)&Cf[(size_t)r * ldc + c];
                float4 bv = *(const float4*)&bias[c];
                float f0 = lrelu(v.x + bv.x), f1 = lrelu(v.y + bv.y);
                float f2 = lrelu(v.z + bv.z), f3 = lrelu(v.w + bv.w);
                __nv_bfloat16 h0, l0, h1, l1, h2, l2, h3, l3;
                split_bf16(f0, h0, l0);
                split_bf16(f1, h1, l1);
                split_bf16(f2, h2, l2);
                split_bf16(f3, h3, l3);
                size_t o = (size_t)r * HID + c;
                *(__nv_bfloat162*)&Ch[o]     = __nv_bfloat162(h0, h1);
                *(__nv_bfloat162*)&Ch[o + 2] = __nv_bfloat162(h2, h3);
                *(__nv_bfloat162*)&Cl[o]     = __nv_bfloat162(l0, l1);
                *(__nv_bfloat162*)&Cl[o + 2] = __nv_bfloat162(l2, l3);
            }
        }
    }
}

// ================= 64x64 mma GEMM (f1/f2) =================
#define B64_AL 9216u
#define B64_BH 18432u
#define B64_BL 27648u
#define BUF64  36864u

template <int EPI>
__global__ void __launch_bounds__(128, 2)
k_mma64(const __nv_bfloat16* __restrict__ Ah, const __nv_bfloat16* __restrict__ Al, int lda,
        const __nv_bfloat16* __restrict__ Bh, const __nv_bfloat16* __restrict__ Bl, int ldb,
        const float* __restrict__ bias,
        float* __restrict__ Cf, __nv_bfloat16* __restrict__ Ch, __nv_bfloat16* __restrict__ Cl,
        int ldc, int nc)
{
    extern __shared__ char smx[];
    const uint32_t smb = smem_u32(smx);
    const int tid = threadIdx.x;
    const int wid = tid >> 5, lane = tid & 31;
    const int wm = wid & 1, wn = wid >> 1;
    const int row0 = blockIdx.y * 64, col0 = blockIdx.x * 64;

    const __nv_bfloat16* pAh = Ah + (size_t)row0 * lda;
    const __nv_bfloat16* pAl = Al + (size_t)row0 * lda;
    const __nv_bfloat16* pBh = Bh + (size_t)col0 * ldb;
    const __nv_bfloat16* pBl = Bl + (size_t)col0 * ldb;

    auto fill = [&](int b, int c) {
        const int kb = c * 64;
        uint32_t base = smb + b * BUF64;
        #pragma unroll
        for (int i = 0; i < 4; i++) {
            int idx = i * 128 + tid;
            int row = idx >> 3, seg = idx & 7;
            uint32_t d = base + (uint32_t)(row * 144 + seg * 16);
            size_t sa = (size_t)row * lda + kb + seg * 8;
            size_t sb = (size_t)row * ldb + kb + seg * 8;
            CP16(d,          pAh + sa);
            CP16(d + B64_AL, pAl + sa);
            CP16(d + B64_BH, pBh + sb);
            CP16(d + B64_BL, pBl + sb);
        }
    };

    float acc[2][4][4];
    #pragma unroll
    for (int i = 0; i < 2; i++)
        #pragma unroll
        for (int j = 0; j < 4; j++)
            #pragma unroll
            for (int q = 0; q < 4; q++) acc[i][j][q] = 0.f;

    const int g2 = lane >> 3, rr = lane & 7;
    const uint32_t aoff = (uint32_t)((wm * 32 + (g2 & 1) * 8 + rr) * 144 + (g2 >> 1) * 16);
    const uint32_t boff = (uint32_t)((wn * 32 + (g2 >> 1) * 8 + rr) * 144 + (g2 & 1) * 16);

    fill(0, 0);
    CP_COMMIT();
    if (nc > 1) { fill(1, 1); CP_COMMIT(); }

    for (int ci = 0; ci < nc; ci++) {
        if (ci + 1 < nc) CP_WAIT1(); else CP_WAIT0();
        __syncthreads();
        if (ci + 2 < nc) { fill((ci + 2) % 3, ci + 2); CP_COMMIT(); }
        uint32_t base = smb + (uint32_t)(ci % 3) * BUF64;
        #pragma unroll
        for (int k16 = 0; k16 < 4; k16++) {
            uint32_t Af[2][4], Lf[2][4], Bf[2][4], Mf[2][4];
            #pragma unroll
            for (int mt = 0; mt < 2; mt++) {
                ldsm4(Af[mt], base + aoff + mt * 2304 + k16 * 32);
                ldsm4(Lf[mt], base + B64_AL + aoff + mt * 2304 + k16 * 32);
            }
            #pragma unroll
            for (int nt2 = 0; nt2 < 2; nt2++) {
                ldsm4(Bf[nt2], base + B64_BH + boff + nt2 * 2304 + k16 * 32);
                ldsm4(Mf[nt2], base + B64_BL + boff + nt2 * 2304 + k16 * 32);
            }
            #pragma unroll
            for (int mt = 0; mt < 2; mt++)
                #pragma unroll
                for (int nt = 0; nt < 4; nt++) {
                    uint32_t bh0 = Bf[nt >> 1][(nt & 1) * 2], bh1 = Bf[nt >> 1][(nt & 1) * 2 + 1];
                    uint32_t bl0 = Mf[nt >> 1][(nt & 1) * 2], bl1 = Mf[nt >> 1][(nt & 1) * 2 + 1];
                    mma16816(acc[mt][nt], Af[mt], bh0, bh1);
                    mma16816(acc[mt][nt], Af[mt], bl0, bl1);
                    mma16816(acc[mt][nt], Lf[mt], bh0, bh1);
                }
        }
        __syncthreads();
    }

    const int g = lane >> 2, t = lane & 3;
    #pragma unroll
    for (int mt = 0; mt < 2; mt++) {
        const int ra = row0 + wm * 32 + mt * 16 + g;
        const int rb = ra + 8;
        #pragma unroll
        for (int nt = 0; nt < 4; nt++) {
            const int c = col0 + wn * 32 + nt * 8 + t * 2;
            float* d = acc[mt][nt];
            float2 bv = *(const float2*)&bias[c];
            float v00 = lrelu(d[0] + bv.x), v01 = lrelu(d[1] + bv.y);
            float v10 = lrelu(d[2] + bv.x), v11 = lrelu(d[3] + bv.y);
            if (EPI == 0) {
                float2 oA = {v00, v01}, oB = {v10, v11};
                *(float2*)&Cf[(size_t)ra * ldc + c] = oA;
                *(float2*)&Cf[(size_t)rb * ldc + c] = oB;
            } else {
                __nv_bfloat16 h00, l00, h01, l01, h10, l10, h11, l11;
                split_bf16(v00, h00, l00);
                split_bf16(v01, h01, l01);
                split_bf16(v10, h10, l10);
                split_bf16(v11, h11, l11);
                *(__nv_bfloat162*)&Ch[(size_t)ra * ldc + c] = __nv_bfloat162(h00, h01);
                *(__nv_bfloat162*)&Cl[(size_t)ra * ldc + c] = __nv_bfloat162(l00, l01);
                *(__nv_bfloat162*)&Ch[(size_t)rb * ldc + c] = __nv_bfloat162(h10, h11);
                *(__nv_bfloat162*)&Cl[(size_t)rb * ldc + c] = __nv_bfloat162(l10, l11);
            }
        }
    }
}

// ---------------- final layer ----------------
__global__ void k_out(const float* __restrict__ A, const float* __restrict__ Wo,
                      const float* __restrict__ bo, float* __restrict__ out)
{
    int b = blockIdx.x;
    int w = threadIdx.x >> 5, lane = threadIdx.x & 31;
    const float* a = A + (size_t)b * HID;
    float s = 0.f;
    for (int k = lane; k < HID; k += 32)
        s += a[k] * Wo[k * OUTD + w];
    #pragma unroll
    for (int o = 16; o > 0; o >>= 1) s += __shfl_xor_sync(0xFFFFFFFFu, s, o);
    __shared__ float sl[OUTD];
    if (lane == 0) sl[w] = s + bo[w];
    __syncthreads();
    if (threadIdx.x == 0) {
        float m = sl[0];
        #pragma unroll
        for (int o = 1; o < OUTD; o++) m = fmaxf(m, sl[o]);
        float sum = 0.f;
        #pragma unroll
        for (int o = 0; o < OUTD; o++) sum += expf(sl[o] - m);
        float l = logf(sum);
        #pragma unroll
        for (int o = 0; o < OUTD; o++) out[b * OUTD + o] = sl[o] - m - l;
    }
}

// ---------------- launch ----------------
static inline int cdiv(int a, int b) { return (a + b - 1) / b; }

extern "C" void kernel_launch(void* const* d_in, const int* in_sizes, int n_in,
                              void* d_out, int out_size)
{
    const float* x   = (const float*)d_in[0];
    const void*  ei  = d_in[1];
    const float* ew  = (const float*)d_in[2];
    const float* W1  = (const float*)d_in[3];
    const float* b1  = (const float*)d_in[4];
    const float* W2  = (const float*)d_in[5];
    const float* b2  = (const float*)d_in[6];
    const float* Wf0 = (const float*)d_in[7];
    const float* bf0 = (const float*)d_in[8];
    const float* Wf1 = (const float*)d_in[9];
    const float* bf1 = (const float*)d_in[10];
    const float* Wf2 = (const float*)d_in[11];
    const float* bf2 = (const float*)d_in[12];
    const float* Wo  = (const float*)d_in[13];
    const float* bo  = (const float*)d_in[14];
    float* out = (float*)d_out;

    __nv_bfloat16 *aggxh, *aggxl, *W1th, *W1tl, *W2th, *W2tl, *agg1h, *agg1l;
    __nv_bfloat16 *xcath, *xcatl, *Wf0th, *Wf0tl, *t0h, *t0l, *Wf1th, *Wf1tl;
    __nv_bfloat16 *t1h, *t1l, *Wf2th, *Wf2tl;
    float *h1, *t0f, *t2;
    cudaGetSymbolAddress((void**)&aggxh, g_aggx_h);
    cudaGetSymbolAddress((void**)&aggxl, g_aggx_l);
    cudaGetSymbolAddress((void**)&W1th,  g_W1t_h);
    cudaGetSymbolAddress((void**)&W1tl,  g_W1t_l);
    cudaGetSymbolAddress((void**)&W2th,  g_W2t_h);
    cudaGetSymbolAddress((void**)&W2tl,  g_W2t_l);
    cudaGetSymbolAddress((void**)&agg1h, g_agg1_h);
    cudaGetSymbolAddress((void**)&agg1l, g_agg1_l);
    cudaGetSymbolAddress((void**)&xcath, g_xcat_h);
    cudaGetSymbolAddress((void**)&xcatl, g_xcat_l);
    cudaGetSymbolAddress((void**)&Wf0th, g_Wf0t_h);
    cudaGetSymbolAddress((void**)&Wf0tl, g_Wf0t_l);
    cudaGetSymbolAddress((void**)&t0h,   g_t0_h);
    cudaGetSymbolAddress((void**)&t0l,   g_t0_l);
    cudaGetSymbolAddress((void**)&Wf1th, g_Wf1t_h);
    cudaGetSymbolAddress((void**)&Wf1tl, g_Wf1t_l);
    cudaGetSymbolAddress((void**)&t1h,   g_t1_h);
    cudaGetSymbolAddress((void**)&t1l,   g_t1_l);
    cudaGetSymbolAddress((void**)&Wf2th, g_Wf2t_h);
    cudaGetSymbolAddress((void**)&Wf2tl, g_Wf2t_l);
    cudaGetSymbolAddress((void**)&h1,    g_h1);
    cudaGetSymbolAddress((void**)&t0f,   g_t0f);
    cudaGetSymbolAddress((void**)&t2,    g_t2);

    const int SMEM   = 3 * (int)BUFSZ;   // 221184
    const int SMEM64 = 3 * (int)BUF64;   // 110592
    cudaFuncSetAttribute(k_mma_gemm<0>, cudaFuncAttributeMaxDynamicSharedMemorySize, SMEM);
    cudaFuncSetAttribute(k_mma_gemm<2>, cudaFuncAttributeMaxDynamicSharedMemorySize, SMEM);
    cudaFuncSetAttribute(k_mma_gemm<3>, cudaFuncAttributeMaxDynamicSharedMemorySize, SMEM);
    cudaFuncSetAttribute(k_mma64<0>, cudaFuncAttributeMaxDynamicSharedMemorySize, SMEM64);
    cudaFuncSetAttribute(k_mma64<1>, cudaFuncAttributeMaxDynamicSharedMemorySize, SMEM64);

    const int TPB = 256;

    // graph normalization + CSR build
    k_setup<<<cdiv(NN, TPB), TPB>>>((const int*)ei);
    k_edges<<<cdiv(EE, TPB), TPB>>>(ei, ew);
    k_scan_dis<<<1, 1024>>>();
    k_fill<<<cdiv(EE, TPB), TPB>>>(ew);

    // all weight transposes in one launch; copyx (+pad +zero t0f) in one launch
    k_wall<<<7104, dim3(32, 8)>>>(W1, W2, Wf1, Wf2, Wf0);
    k_copyx<<<cdiv(NN * FEA + BGR * 24 + BGR * HID, TPB), TPB>>>(x);

    // conv1
    k_gather1<<<NN, 64>>>(x);
    k_mma_gemm<0><<<dim3(4, 176, 1), 256, SMEM>>>(
        aggxh, aggxl, 64, W1th, W1tl, 64, b1, h1, nullptr, nullptr, HID, 1, 1);

    // conv2 (epilogue scatters into xcat layout)
    k_gather2<<<NN, 128>>>();
    k_mma_gemm<2><<<dim3(4, 176, 1), 256, SMEM>>>(
        agg1h, agg1l, HID, W2th, W2tl, HID, b2, nullptr, xcath, xcatl, 0, 8, 8);

    // f0: split-K=8 atomic reduce + in-kernel last-CTA finalize (bias+lrelu+split)
    k_mma_gemm<3><<<dim3(4, 8, 8), 256, SMEM>>>(
        xcath, xcatl, KP0, Wf0th, Wf0tl, KP0, bf0, t0f, t0h, t0l, HID, NCH0, 25);

    // f1, f2
    k_mma64<1><<<dim3(8, 16), 128, SMEM64>>>(
        t0h, t0l, HID, Wf1th, Wf1tl, HID, bf1, nullptr, t1h, t1l, HID, 8);
    k_mma64<0><<<dim3(8, 16), 128, SMEM64>>>(
        t1h, t1l, HID, Wf2th, Wf2tl, HID, bf2, t2, nullptr, nullptr, HID, 8);

    // output head + log_softmax
    k_out<<<BGR, 128>>>(t2, Wo, bo, out);
}

// round 9
// speedup vs baseline: 1.0583x; 1.0583x over previous
#include <cuda_runtime.h>
#include <cuda_bf16.h>
#include <cstdint>

#define NN   22528
#define EE   360448
#define FEA  60
#define HID  512
#define OUTD 4
#define MA   22
#define BGR  1024
#define CAT  572
#define FLAT 12584
#define KP0  12608
#define NCH0 197

// ---------------- device scratch ----------------
__device__ int   g_flag;
__device__ float g_dis[NN];
__device__ int   g_row[EE];
__device__ int   g_col[EE];
__device__ int   g_cnt[NN];
__device__ int   g_cur[NN];
__device__ int   g_off[NN + 1];
__device__ int   g_src[EE];
__device__ float g_w[EE];            // raw ew after fill; scaled on the fly in gathers

__device__ __align__(16) __nv_bfloat16 g_aggx_h[(size_t)NN * 64];
__device__ __align__(16) __nv_bfloat16 g_aggx_l[(size_t)NN * 64];
__device__ __align__(16) __nv_bfloat16 g_W1t_h[512 * 64];
__device__ __align__(16) __nv_bfloat16 g_W1t_l[512 * 64];
__device__ __align__(16) float         g_h1[(size_t)NN * HID];
__device__ __align__(16) __nv_bfloat16 g_W2t_h[512 * 512];
__device__ __align__(16) __nv_bfloat16 g_W2t_l[512 * 512];
__device__ __align__(16) __nv_bfloat16 g_agg1_h[(size_t)NN * HID];
__device__ __align__(16) __nv_bfloat16 g_agg1_l[(size_t)NN * HID];
__device__ __align__(16) __nv_bfloat16 g_xcat_h[(size_t)BGR * KP0];
__device__ __align__(16) __nv_bfloat16 g_xcat_l[(size_t)BGR * KP0];
__device__ __align__(16) __nv_bfloat16 g_Wf0t_h[(size_t)512 * KP0];
__device__ __align__(16) __nv_bfloat16 g_Wf0t_l[(size_t)512 * KP0];
__device__ __align__(16) float         g_t0f[BGR * HID];
__device__ __align__(16) __nv_bfloat16 g_t0_h[BGR * HID];
__device__ __align__(16) __nv_bfloat16 g_t0_l[BGR * HID];
__device__ __align__(16) __nv_bfloat16 g_Wf1t_h[512 * 512];
__device__ __align__(16) __nv_bfloat16 g_Wf1t_l[512 * 512];
__device__ __align__(16) __nv_bfloat16 g_t1_h[BGR * HID];
__device__ __align__(16) __nv_bfloat16 g_t1_l[BGR * HID];
__device__ __align__(16) __nv_bfloat16 g_Wf2t_h[512 * 512];
__device__ __align__(16) __nv_bfloat16 g_Wf2t_l[512 * 512];
__device__ __align__(16) float         g_t2[BGR * HID];

// ---------------- helpers ----------------
__device__ __forceinline__ uint32_t smem_u32(const void* p) {
    uint32_t a;
    asm("{ .reg .u64 t; cvta.to.shared.u64 t, %1; cvt.u32.u64 %0, t; }" : "=r"(a) : "l"(p));
    return a;
}
__device__ __forceinline__ void ldsm4(uint32_t* r, uint32_t addr) {
    asm volatile("ldmatrix.sync.aligned.m8n8.x4.shared.b16 {%0,%1,%2,%3}, [%4];"
        : "=r"(r[0]), "=r"(r[1]), "=r"(r[2]), "=r"(r[3]) : "r"(addr));
}
__device__ __forceinline__ void mma16816(float* d, const uint32_t* a, uint32_t b0, uint32_t b1) {
    asm volatile("mma.sync.aligned.m16n8k16.row.col.f32.bf16.bf16.f32 "
        "{%0,%1,%2,%3}, {%4,%5,%6,%7}, {%8,%9}, {%0,%1,%2,%3};"
        : "+f"(d[0]), "+f"(d[1]), "+f"(d[2]), "+f"(d[3])
        : "r"(a[0]), "r"(a[1]), "r"(a[2]), "r"(a[3]), "r"(b0), "r"(b1));
}
#define CP16(d, s)   asm volatile("cp.async.cg.shared.global [%0], [%1], 16;" :: "r"(d), "l"(s))
#define CP_COMMIT()  asm volatile("cp.async.commit_group;" ::: "memory")
#define CP_WAIT0()   asm volatile("cp.async.wait_group 0;" ::: "memory")
#define CP_WAIT1()   asm volatile("cp.async.wait_group 1;" ::: "memory")

__device__ __forceinline__ float lrelu(float v) { return v > 0.f ? v : 0.01f * v; }
__device__ __forceinline__ void split_bf16(float v, __nv_bfloat16& h, __nv_bfloat16& l) {
    h = __float2bfloat16(v);
    l = __float2bfloat16(v - __bfloat162float(h));
}

// ---------------- setup ----------------
__global__ void k_setup(const int* ei) {
    int i = blockIdx.x * blockDim.x + threadIdx.x;
    if (i < NN) { g_cnt[i] = 0; g_cur[i] = 0; }
    if (i == 0) {
        int f = 1;
        for (int j = 0; j < 64; j++)
            if (ei[2 * j + 1] != 0) { f = 0; break; }
        g_flag = f;
    }
}
// counts only — no deg atomics, no ew read
__global__ void k_edges(const void* ei) {
    int e = blockIdx.x * blockDim.x + threadIdx.x;
    if (e >= EE) return;
    int r, c;
    if (g_flag) {
        const long long* p = (const long long*)ei;
        r = (int)p[e]; c = (int)p[EE + e];
    } else {
        const int* p = (const int*)ei;
        r = p[e]; c = p[EE + e];
    }
    g_row[e] = r; g_col[e] = c;
    atomicAdd(&g_cnt[c], 1);
}
__global__ void k_scan() {
    __shared__ int sh[1024];
    int t = threadIdx.x;
    int base = t * 22;
    int local[22];
    int s = 0;
    #pragma unroll
    for (int i = 0; i < 22; i++) { local[i] = g_cnt[base + i]; s += local[i]; }
    sh[t] = s;
    __syncthreads();
    for (int off = 1; off < 1024; off <<= 1) {
        int v = (t >= off) ? sh[t - off] : 0;
        __syncthreads();
        sh[t] += v;
        __syncthreads();
    }
    int pre = (t == 0) ? 0 : sh[t - 1];
    #pragma unroll
    for (int i = 0; i < 22; i++) { g_off[base + i] = pre; pre += local[i]; }
    if (t == 0) g_off[NN] = EE;
}
// bucket fill with RAW edge weights (no dis dependency)
__global__ void k_fill(const float* __restrict__ ew) {
    int e = blockIdx.x * blockDim.x + threadIdx.x;
    if (e >= EE) return;
    int c = g_col[e];
    int p = g_off[c] + atomicAdd(&g_cur[c], 1);
    g_src[p] = g_row[e];
    g_w[p] = ew[e];
}
// deg from CSR (streaming, no atomics): deg = 1 + sum(ew); dis = rsqrt(deg)
__global__ void k_dis2() {
    int n = blockIdx.x * blockDim.x + threadIdx.x;
    if (n >= NN) return;
    float s = 1.0f;
    int a = g_off[n], b = g_off[n + 1];
    for (int p = a; p < b; p++) s += g_w[p];
    g_dis[n] = rsqrtf(s);
}

// ---------------- CSR gathers (normalization applied on the fly) ----------------
// agg[n] = dis_n * ( dis_n * x[n] + sum_p ew_p * dis[src_p] * x[src_p] )
__global__ void k_gather1(const float* __restrict__ x) {
    int n = blockIdx.x;
    int f = threadIdx.x;               // 64
    float dn = g_dis[n];
    float acc = 0.f;
    if (f < FEA) acc = dn * x[(size_t)n * FEA + f];
    int s = g_off[n], e = g_off[n + 1];
    for (int p = s; p < e; p++) {
        int src = g_src[p];
        float w = g_w[p] * g_dis[src];
        if (f < FEA) acc += x[(size_t)src * FEA + f] * w;
    }
    acc *= dn;
    if (f >= FEA) acc = 0.f;
    __nv_bfloat16 h, l;
    split_bf16(acc, h, l);
    g_aggx_h[(size_t)n * 64 + f] = h;
    g_aggx_l[(size_t)n * 64 + f] = l;
}

__global__ void k_gather2() {
    int n = blockIdx.x;
    int f4 = threadIdx.x;              // 128 threads, float4 each
    float dn = g_dis[n];
    float4 acc = ((const float4*)(g_h1 + (size_t)n * HID))[f4];
    acc.x *= dn; acc.y *= dn; acc.z *= dn; acc.w *= dn;
    int s = g_off[n], e = g_off[n + 1];
    for (int p = s; p < e; p++) {
        int src = g_src[p];
        float w = g_w[p] * g_dis[src];
        float4 v = ((const float4*)(g_h1 + (size_t)src * HID))[f4];
        acc.x += v.x * w; acc.y += v.y * w;
        acc.z += v.z * w; acc.w += v.w * w;
    }
    acc.x *= dn; acc.y *= dn; acc.z *= dn; acc.w *= dn;
    __nv_bfloat16 h0, l0, h1b, l1, h2, l2, h3, l3;
    split_bf16(acc.x, h0, l0);
    split_bf16(acc.y, h1b, l1);
    split_bf16(acc.z, h2, l2);
    split_bf16(acc.w, h3, l3);
    size_t o = (size_t)n * HID + f4 * 4;
    *(__nv_bfloat162*)&g_agg1_h[o]     = __nv_bfloat162(h0, h1b);
    *(__nv_bfloat162*)&g_agg1_h[o + 2] = __nv_bfloat162(h2, h3);
    *(__nv_bfloat162*)&g_agg1_l[o]     = __nv_bfloat162(l0, l1);
    *(__nv_bfloat162*)&g_agg1_l[o + 2] = __nv_bfloat162(l2, l3);
}

// ---------------- weight transpose + split ----------------
__global__ void k_wtrans(const float* __restrict__ W, int K, int Kpad,
                         __nv_bfloat16* __restrict__ oh, __nv_bfloat16* __restrict__ ol) {
    __shared__ float tile[32][33];
    int kb = blockIdx.x * 32, nb = blockIdx.y * 32;
    int tx = threadIdx.x, ty = threadIdx.y;   // 32 x 8
    #pragma unroll
    for (int i = 0; i < 4; i++) {
        int row = kb + ty + i * 8;
        tile[ty + i * 8][tx] = (row < K) ? W[(size_t)row * 512 + nb + tx] : 0.f;
    }
    __syncthreads();
    #pragma unroll
    for (int i = 0; i < 4; i++) {
        int n = nb + ty + i * 8;
        int k = kb + tx;
        float v = tile[tx][ty + i * 8];
        __nv_bfloat16 h, l;
        split_bf16(v, h, l);
        oh[(size_t)n * Kpad + k] = h;
        ol[(size_t)n * Kpad + k] = l;
    }
}
__global__ void k_wtrans3(const float* __restrict__ Wa, const float* __restrict__ Wb,
                          const float* __restrict__ Wc,
                          __nv_bfloat16* __restrict__ oha, __nv_bfloat16* __restrict__ ola,
                          __nv_bfloat16* __restrict__ ohb, __nv_bfloat16* __restrict__ olb,
                          __nv_bfloat16* __restrict__ ohc, __nv_bfloat16* __restrict__ olc) {
    __shared__ float tile[32][33];
    const float* W = (blockIdx.z == 0) ? Wa : (blockIdx.z == 1) ? Wb : Wc;
    __nv_bfloat16* oh = (blockIdx.z == 0) ? oha : (blockIdx.z == 1) ? ohb : ohc;
    __nv_bfloat16* ol = (blockIdx.z == 0) ? ola : (blockIdx.z == 1) ? olb : olc;
    int kb = blockIdx.x * 32, nb = blockIdx.y * 32;
    int tx = threadIdx.x, ty = threadIdx.y;
    #pragma unroll
    for (int i = 0; i < 4; i++)
        tile[ty + i * 8][tx] = W[(size_t)(kb + ty + i * 8) * 512 + nb + tx];
    __syncthreads();
    #pragma unroll
    for (int i = 0; i < 4; i++) {
        int n = nb + ty + i * 8;
        int k = kb + tx;
        float v = tile[tx][ty + i * 8];
        __nv_bfloat16 h, l;
        split_bf16(v, h, l);
        oh[(size_t)n * 512 + k] = h;
        ol[(size_t)n * 512 + k] = l;
    }
}

// copy raw x into xcat (split) + zero pad cols
__global__ void k_copyx(const float* __restrict__ x) {
    int t = blockIdx.x * blockDim.x + threadIdx.x;
    if (t < NN * FEA) {
        int n = t / FEA, f = t - n * FEA;
        int b = n / MA, j = n - b * MA;
        size_t o = (size_t)b * KP0 + j * CAT + HID + f;
        __nv_bfloat16 h, l;
        split_bf16(x[t], h, l);
        g_xcat_h[o] = h;
        g_xcat_l[o] = l;
    } else if (t < NN * FEA + BGR * 24) {
        int t2 = t - NN * FEA;
        int b = t2 / 24, f = t2 - b * 24;
        size_t o = (size_t)b * KP0 + FLAT + f;
        g_xcat_h[o] = __float2bfloat16(0.f);
        g_xcat_l[o] = __float2bfloat16(0.f);
    }
}
__global__ void k_zero_t0f() {
    int t = blockIdx.x * blockDim.x + threadIdx.x;
    if (t < BGR * HID) g_t0f[t] = 0.f;
}
__global__ void k_fin_t0(const float* __restrict__ bias) {
    int t = blockIdx.x * blockDim.x + threadIdx.x;
    if (t >= BGR * HID) return;
    int c = t & 511;
    float v = lrelu(g_t0f[t] + bias[c]);
    __nv_bfloat16 h, l;
    split_bf16(v, h, l);
    g_t0_h[t] = h;
    g_t0_l[t] = l;
}

// ================= 128x128 mma GEMM, 3-stage cp.async =================
// EPI: 0 fp32+bias+lrelu, 2 xcat-scatter, 3 atomicAdd raw.
#define OFF_AL 18432u
#define OFF_BH 36864u
#define OFF_BL 55296u
#define BUFSZ  73728u

template <int EPI>
__global__ void __launch_bounds__(256, 1)
k_mma_gemm(const __nv_bfloat16* __restrict__ Ah, const __nv_bfloat16* __restrict__ Al, int lda,
           const __nv_bfloat16* __restrict__ Bh, const __nv_bfloat16* __restrict__ Bl, int ldb,
           const float* __restrict__ bias,
           float* __restrict__ Cf, __nv_bfloat16* __restrict__ Ch, __nv_bfloat16* __restrict__ Cl,
           int ldc, int nch, int cper)
{
    extern __shared__ char smx[];
    const uint32_t smb = smem_u32(smx);
    const int tid = threadIdx.x;
    const int wid = tid >> 5, lane = tid & 31;
    const int wm = wid & 1, wn = wid >> 1;
    const int row0 = blockIdx.y * 128, col0 = blockIdx.x * 128;
    const int c0 = blockIdx.z * cper;
    const int nc = min(nch, c0 + cper) - c0;

    const __nv_bfloat16* pAh = Ah + (size_t)row0 * lda;
    const __nv_bfloat16* pAl = Al + (size_t)row0 * lda;
    const __nv_bfloat16* pBh = Bh + (size_t)col0 * ldb;
    const __nv_bfloat16* pBl = Bl + (size_t)col0 * ldb;

    auto fill = [&](int b, int c) {
        const int kb = c * 64;
        uint32_t base = smb + b * BUFSZ;
        #pragma unroll
        for (int i = 0; i < 4; i++) {
            int idx = i * 256 + tid;
            int row = idx >> 3, seg = idx & 7;
            uint32_t d = base + (uint32_t)(row * 144 + seg * 16);
            size_t sa = (size_t)row * lda + kb + seg * 8;
            size_t sb = (size_t)row * ldb + kb + seg * 8;
            CP16(d,          pAh + sa);
            CP16(d + OFF_AL, pAl + sa);
            CP16(d + OFF_BH, pBh + sb);
            CP16(d + OFF_BL, pBl + sb);
        }
    };

    float acc[4][4][4];
    #pragma unroll
    for (int i = 0; i < 4; i++)
        #pragma unroll
        for (int j = 0; j < 4; j++)
            #pragma unroll
            for (int q = 0; q < 4; q++) acc[i][j][q] = 0.f;

    const int g2 = lane >> 3, rr = lane & 7;
    const uint32_t aoff = (uint32_t)((wm * 64 + (g2 & 1) * 8 + rr) * 144 + (g2 >> 1) * 16);
    const uint32_t boff = (uint32_t)((wn * 32 + (g2 >> 1) * 8 + rr) * 144 + (g2 & 1) * 16);

    fill(0, c0);
    CP_COMMIT();
    if (nc > 1) { fill(1, c0 + 1); CP_COMMIT(); }

    for (int ci = 0; ci < nc; ci++) {
        if (ci + 1 < nc) CP_WAIT1(); else CP_WAIT0();
        __syncthreads();
        if (ci + 2 < nc) { fill((ci + 2) % 3, c0 + ci + 2); CP_COMMIT(); }
        uint32_t base = smb + (uint32_t)(ci % 3) * BUFSZ;
        #pragma unroll
        for (int k16 = 0; k16 < 4; k16++) {
            uint32_t Af[4][4], Lf[4][4], Bf[2][4], Mf[2][4];
            #pragma unroll
            for (int mt = 0; mt < 4; mt++) {
                ldsm4(Af[mt], base + aoff + mt * 2304 + k16 * 32);
                ldsm4(Lf[mt], base + OFF_AL + aoff + mt * 2304 + k16 * 32);
            }
            #pragma unroll
            for (int nt2 = 0; nt2 < 2; nt2++) {
                ldsm4(Bf[nt2], base + OFF_BH + boff + nt2 * 2304 + k16 * 32);
                ldsm4(Mf[nt2], base + OFF_BL + boff + nt2 * 2304 + k16 * 32);
            }
            #pragma unroll
            for (int mt = 0; mt < 4; mt++)
                #pragma unroll
                for (int nt = 0; nt < 4; nt++) {
                    uint32_t bh0 = Bf[nt >> 1][(nt & 1) * 2], bh1 = Bf[nt >> 1][(nt & 1) * 2 + 1];
                    uint32_t bl0 = Mf[nt >> 1][(nt & 1) * 2], bl1 = Mf[nt >> 1][(nt & 1) * 2 + 1];
                    mma16816(acc[mt][nt], Af[mt], bh0, bh1);
                    mma16816(acc[mt][nt], Af[mt], bl0, bl1);
                    mma16816(acc[mt][nt], Lf[mt], bh0, bh1);
                }
        }
        __syncthreads();
    }

    const int g = lane >> 2, t = lane & 3;
    #pragma unroll
    for (int mt = 0; mt < 4; mt++) {
        const int ra = row0 + wm * 64 + mt * 16 + g;
        const int rb = ra + 8;
        size_t oa = 0, ob = 0;
        if (EPI == 2) {
            int bg = ra / MA, j = ra - bg * MA;
            oa = (size_t)bg * KP0 + (size_t)j * CAT;
            bg = rb / MA; j = rb - bg * MA;
            ob = (size_t)bg * KP0 + (size_t)j * CAT;
        }
        #pragma unroll
        for (int nt = 0; nt < 4; nt++) {
            const int c = col0 + wn * 32 + nt * 8 + t * 2;
            float* d = acc[mt][nt];
            if (EPI == 3) {
                atomicAdd(&Cf[(size_t)ra * ldc + c],     d[0]);
                atomicAdd(&Cf[(size_t)ra * ldc + c + 1], d[1]);
                atomicAdd(&Cf[(size_t)rb * ldc + c],     d[2]);
                atomicAdd(&Cf[(size_t)rb * ldc + c + 1], d[3]);
            } else {
                float2 bv = *(const float2*)&bias[c];
                float v00 = lrelu(d[0] + bv.x), v01 = lrelu(d[1] + bv.y);
                float v10 = lrelu(d[2] + bv.x), v11 = lrelu(d[3] + bv.y);
                if (EPI == 0) {
                    float2 oA = {v00, v01}, oB = {v10, v11};
                    *(float2*)&Cf[(size_t)ra * ldc + c] = oA;
                    *(float2*)&Cf[(size_t)rb * ldc + c] = oB;
                } else {
                    __nv_bfloat16 h00, l00, h01, l01, h10, l10, h11, l11;
                    split_bf16(v00, h00, l00);
                    split_bf16(v01, h01, l01);
                    split_bf16(v10, h10, l10);
                    split_bf16(v11, h11, l11);
                    *(__nv_bfloat162*)&Ch[oa + c] = __nv_bfloat162(h00, h01);
                    *(__nv_bfloat162*)&Cl[oa + c] = __nv_bfloat162(l00, l01);
                    *(__nv_bfloat162*)&Ch[ob + c] = __nv_bfloat162(h10, h11);
                    *(__nv_bfloat162*)&Cl[ob + c] = __nv_bfloat162(l10, l11);
                }
            }
        }
    }
}

// ================= 64x64 mma GEMM (f1/f2) =================
#define B64_AL 9216u
#define B64_BH 18432u
#define B64_BL 27648u
#define BUF64  36864u

template <int EPI>
__global__ void __launch_bounds__(128, 2)
k_mma64(const __nv_bfloat16* __restrict__ Ah, const __nv_bfloat16* __restrict__ Al, int lda,
        const __nv_bfloat16* __restrict__ Bh, const __nv_bfloat16* __restrict__ Bl, int ldb,
        const float* __restrict__ bias,
        float* __restrict__ Cf, __nv_bfloat16* __restrict__ Ch, __nv_bfloat16* __restrict__ Cl,
        int ldc, int nc)
{
    extern __shared__ char smx[];
    const uint32_t smb = smem_u32(smx);
    const int tid = threadIdx.x;
    const int wid = tid >> 5, lane = tid & 31;
    const int wm = wid & 1, wn = wid >> 1;
    const int row0 = blockIdx.y * 64, col0 = blockIdx.x * 64;

    const __nv_bfloat16* pAh = Ah + (size_t)row0 * lda;
    const __nv_bfloat16* pAl = Al + (size_t)row0 * lda;
    const __nv_bfloat16* pBh = Bh + (size_t)col0 * ldb;
    const __nv_bfloat16* pBl = Bl + (size_t)col0 * ldb;

    auto fill = [&](int b, int c) {
        const int kb = c * 64;
        uint32_t base = smb + b * BUF64;
        #pragma unroll
        for (int i = 0; i < 4; i++) {
            int idx = i * 128 + tid;
            int row = idx >> 3, seg = idx & 7;
            uint32_t d = base + (uint32_t)(row * 144 + seg * 16);
            size_t sa = (size_t)row * lda + kb + seg * 8;
            size_t sb = (size_t)row * ldb + kb + seg * 8;
            CP16(d,          pAh + sa);
            CP16(d + B64_AL, pAl + sa);
            CP16(d + B64_BH, pBh + sb);
            CP16(d + B64_BL, pBl + sb);
        }
    };

    float acc[2][4][4];
    #pragma unroll
    for (int i = 0; i < 2; i++)
        #pragma unroll
        for (int j = 0; j < 4; j++)
            #pragma unroll
            for (int q = 0; q < 4; q++) acc[i][j][q] = 0.f;

    const int g2 = lane >> 3, rr = lane & 7;
    const uint32_t aoff = (uint32_t)((wm * 32 + (g2 & 1) * 8 + rr) * 144 + (g2 >> 1) * 16);
    const uint32_t boff = (uint32_t)((wn * 32 + (g2 >> 1) * 8 + rr) * 144 + (g2 & 1) * 16);

    fill(0, 0);
    CP_COMMIT();
    if (nc > 1) { fill(1, 1); CP_COMMIT(); }

    for (int ci = 0; ci < nc; ci++) {
        if (ci + 1 < nc) CP_WAIT1(); else CP_WAIT0();
        __syncthreads();
        if (ci + 2 < nc) { fill((ci + 2) % 3, ci + 2); CP_COMMIT(); }
        uint32_t base = smb + (uint32_t)(ci % 3) * BUF64;
        #pragma unroll
        for (int k16 = 0; k16 < 4; k16++) {
            uint32_t Af[2][4], Lf[2][4], Bf[2][4], Mf[2][4];
            #pragma unroll
            for (int mt = 0; mt < 2; mt++) {
                ldsm4(Af[mt], base + aoff + mt * 2304 + k16 * 32);
                ldsm4(Lf[mt], base + B64_AL + aoff + mt * 2304 + k16 * 32);
            }
            #pragma unroll
            for (int nt2 = 0; nt2 < 2; nt2++) {
                ldsm4(Bf[nt2], base + B64_BH + boff + nt2 * 2304 + k16 * 32);
                ldsm4(Mf[nt2], base + B64_BL + boff + nt2 * 2304 + k16 * 32);
            }
            #pragma unroll
            for (int mt = 0; mt < 2; mt++)
                #pragma unroll
                for (int nt = 0; nt < 4; nt++) {
                    uint32_t bh0 = Bf[nt >> 1][(nt & 1) * 2], bh1 = Bf[nt >> 1][(nt & 1) * 2 + 1];
                    uint32_t bl0 = Mf[nt >> 1][(nt & 1) * 2], bl1 = Mf[nt >> 1][(nt & 1) * 2 + 1];
                    mma16816(acc[mt][nt], Af[mt], bh0, bh1);
                    mma16816(acc[mt][nt], Af[mt], bl0, bl1);
                    mma16816(acc[mt][nt], Lf[mt], bh0, bh1);
                }
        }
        __syncthreads();
    }

    const int g = lane >> 2, t = lane & 3;
    #pragma unroll
    for (int mt = 0; mt < 2; mt++) {
        const int ra = row0 + wm * 32 + mt * 16 + g;
        const int rb = ra + 8;
        #pragma unroll
        for (int nt = 0; nt < 4; nt++) {
            const int c = col0 + wn * 32 + nt * 8 + t * 2;
            float* d = acc[mt][nt];
            float2 bv = *(const float2*)&bias[c];
            float v00 = lrelu(d[0] + bv.x), v01 = lrelu(d[1] + bv.y);
            float v10 = lrelu(d[2] + bv.x), v11 = lrelu(d[3] + bv.y);
            if (EPI == 0) {
                float2 oA = {v00, v01}, oB = {v10, v11};
                *(float2*)&Cf[(size_t)ra * ldc + c] = oA;
                *(float2*)&Cf[(size_t)rb * ldc + c] = oB;
            } else {
                __nv_bfloat16 h00, l00, h01, l01, h10, l10, h11, l11;
                split_bf16(v00, h00, l00);
                split_bf16(v01, h01, l01);
                split_bf16(v10, h10, l10);
                split_bf16(v11, h11, l11);
                *(__nv_bfloat162*)&Ch[(size_t)ra * ldc + c] = __nv_bfloat162(h00, h01);
                *(__nv_bfloat162*)&Cl[(size_t)ra * ldc + c] = __nv_bfloat162(l00, l01);
                *(__nv_bfloat162*)&Ch[(size_t)rb * ldc + c] = __nv_bfloat162(h10, h11);
                *(__nv_bfloat162*)&Cl[(size_t)rb * ldc + c] = __nv_bfloat162(l10, l11);
            }
        }
    }
}

// ---------------- final layer ----------------
__global__ void k_out(const float* __restrict__ A, const float* __restrict__ Wo,
                      const float* __restrict__ bo, float* __restrict__ out)
{
    int b = blockIdx.x;
    int w = threadIdx.x >> 5, lane = threadIdx.x & 31;
    const float* a = A + (size_t)b * HID;
    float s = 0.f;
    for (int k = lane; k < HID; k += 32)
        s += a[k] * Wo[k * OUTD + w];
    #pragma unroll
    for (int o = 16; o > 0; o >>= 1) s += __shfl_xor_sync(0xFFFFFFFFu, s, o);
    __shared__ float sl[OUTD];
    if (lane == 0) sl[w] = s + bo[w];
    __syncthreads();
    if (threadIdx.x == 0) {
        float m = sl[0];
        #pragma unroll
        for (int o = 1; o < OUTD; o++) m = fmaxf(m, sl[o]);
        float sum = 0.f;
        #pragma unroll
        for (int o = 0; o < OUTD; o++) sum += expf(sl[o] - m);
        float l = logf(sum);
        #pragma unroll
        for (int o = 0; o < OUTD; o++) out[b * OUTD + o] = sl[o] - m - l;
    }
}

// ---------------- launch ----------------
static inline int cdiv(int a, int b) { return (a + b - 1) / b; }

extern "C" void kernel_launch(void* const* d_in, const int* in_sizes, int n_in,
                              void* d_out, int out_size)
{
    const float* x   = (const float*)d_in[0];
    const void*  ei  = d_in[1];
    const float* ew  = (const float*)d_in[2];
    const float* W1  = (const float*)d_in[3];
    const float* b1  = (const float*)d_in[4];
    const float* W2  = (const float*)d_in[5];
    const float* b2  = (const float*)d_in[6];
    const float* Wf0 = (const float*)d_in[7];
    const float* bf0 = (const float*)d_in[8];
    const float* Wf1 = (const float*)d_in[9];
    const float* bf1 = (const float*)d_in[10];
    const float* Wf2 = (const float*)d_in[11];
    const float* bf2 = (const float*)d_in[12];
    const float* Wo  = (const float*)d_in[13];
    const float* bo  = (const float*)d_in[14];
    float* out = (float*)d_out;

    __nv_bfloat16 *aggxh, *aggxl, *W1th, *W1tl, *W2th, *W2tl, *agg1h, *agg1l;
    __nv_bfloat16 *xcath, *xcatl, *Wf0th, *Wf0tl, *t0h, *t0l, *Wf1th, *Wf1tl;
    __nv_bfloat16 *t1h, *t1l, *Wf2th, *Wf2tl;
    float *h1, *t0f, *t2;
    cudaGetSymbolAddress((void**)&aggxh, g_aggx_h);
    cudaGetSymbolAddress((void**)&aggxl, g_aggx_l);
    cudaGetSymbolAddress((void**)&W1th,  g_W1t_h);
    cudaGetSymbolAddress((void**)&W1tl,  g_W1t_l);
    cudaGetSymbolAddress((void**)&W2th,  g_W2t_h);
    cudaGetSymbolAddress((void**)&W2tl,  g_W2t_l);
    cudaGetSymbolAddress((void**)&agg1h, g_agg1_h);
    cudaGetSymbolAddress((void**)&agg1l, g_agg1_l);
    cudaGetSymbolAddress((void**)&xcath, g_xcat_h);
    cudaGetSymbolAddress((void**)&xcatl, g_xcat_l);
    cudaGetSymbolAddress((void**)&Wf0th, g_Wf0t_h);
    cudaGetSymbolAddress((void**)&Wf0tl, g_Wf0t_l);
    cudaGetSymbolAddress((void**)&t0h,   g_t0_h);
    cudaGetSymbolAddress((void**)&t0l,   g_t0_l);
    cudaGetSymbolAddress((void**)&Wf1th, g_Wf1t_h);
    cudaGetSymbolAddress((void**)&Wf1tl, g_Wf1t_l);
    cudaGetSymbolAddress((void**)&t1h,   g_t1_h);
    cudaGetSymbolAddress((void**)&t1l,   g_t1_l);
    cudaGetSymbolAddress((void**)&Wf2th, g_Wf2t_h);
    cudaGetSymbolAddress((void**)&Wf2tl, g_Wf2t_l);
    cudaGetSymbolAddress((void**)&h1,    g_h1);
    cudaGetSymbolAddress((void**)&t0f,   g_t0f);
    cudaGetSymbolAddress((void**)&t2,    g_t2);

    const int SMEM   = 3 * (int)BUFSZ;   // 221184
    const int SMEM64 = 3 * (int)BUF64;   // 110592
    cudaFuncSetAttribute(k_mma_gemm<0>, cudaFuncAttributeMaxDynamicSharedMemorySize, SMEM);
    cudaFuncSetAttribute(k_mma_gemm<2>, cudaFuncAttributeMaxDynamicSharedMemorySize, SMEM);
    cudaFuncSetAttribute(k_mma_gemm<3>, cudaFuncAttributeMaxDynamicSharedMemorySize, SMEM);
    cudaFuncSetAttribute(k_mma64<0>, cudaFuncAttributeMaxDynamicSharedMemorySize, SMEM64);
    cudaFuncSetAttribute(k_mma64<1>, cudaFuncAttributeMaxDynamicSharedMemorySize, SMEM64);

    const int TPB = 256;

    // CSR build: counts -> scan -> fill(raw ew) -> dis from CSR (no deg atomics)
    k_setup<<<cdiv(NN, TPB), TPB>>>((const int*)ei);
    k_edges<<<cdiv(EE, TPB), TPB>>>(ei);
    k_scan<<<1, 1024>>>();
    k_fill<<<cdiv(EE, TPB), TPB>>>(ew);
    k_dis2<<<cdiv(NN, TPB), TPB>>>();

    // weight transposes + split conversion
    {
        dim3 blk(32, 8);
        k_wtrans<<<dim3(2, 16), blk>>>(W1, FEA, 64, W1th, W1tl);
        k_wtrans<<<dim3(KP0 / 32, 16), blk>>>(Wf0, FLAT, KP0, Wf0th, Wf0tl);
        k_wtrans3<<<dim3(16, 16, 3), blk>>>(W2, Wf1, Wf2,
                                            W2th, W2tl, Wf1th, Wf1tl, Wf2th, Wf2tl);
    }
    k_zero_t0f<<<cdiv(BGR * HID, TPB), TPB>>>();

    // conv1
    k_gather1<<<NN, 64>>>(x);
    k_mma_gemm<0><<<dim3(4, 176, 1), 256, SMEM>>>(
        aggxh, aggxl, 64, W1th, W1tl, 64, b1, h1, nullptr, nullptr, HID, 1, 1);

    // conv2 (epilogue scatters into xcat layout)
    k_gather2<<<NN, 128>>>();
    k_copyx<<<cdiv(NN * FEA + BGR * 24, TPB), TPB>>>(x);
    k_mma_gemm<2><<<dim3(4, 176, 1), 256, SMEM>>>(
        agg1h, agg1l, HID, W2th, W2tl, HID, b2, nullptr, xcath, xcatl, 0, 8, 8);

    // f0: split-K=8 with fp32 atomic reduce, then bias+lrelu+split
    k_mma_gemm<3><<<dim3(4, 8, 8), 256, SMEM>>>(
        xcath, xcatl, KP0, Wf0th, Wf0tl, KP0, nullptr, t0f, nullptr, nullptr, HID, NCH0, 25);
    k_fin_t0<<<cdiv(BGR * HID, TPB), TPB>>>(bf0);

    // f1, f2: 64x64 tiles, direct epilogues
    k_mma64<1><<<dim3(8, 16), 128, SMEM64>>>(
        t0h, t0l, HID, Wf1th, Wf1tl, HID, bf1, nullptr, t1h, t1l, HID, 8);
    k_mma64<0><<<dim3(8, 16), 128, SMEM64>>>(
        t1h, t1l, HID, Wf2th, Wf2tl, HID, bf2, t2, nullptr, nullptr, HID, 8);

    // output head + log_softmax
    k_out<<<BGR, 128>>>(t2, Wo, bo, out);
}

// round 12
// speedup vs baseline: 1.2827x; 1.2121x over previous
#include <cuda_runtime.h>
#include <cuda_fp16.h>
#include <cstdint>

#define NN   22528
#define EE   360448
#define FEA  60
#define HID  512
#define OUTD 4
#define MA   22
#define BGR  1024
#define CAT  572
#define FLAT 12584
#define KP0  12608
#define NCH0 197

// ---------------- device scratch ----------------
__device__ int   g_flag;
__device__ float g_dis[NN];
__device__ int   g_row[EE];
__device__ int   g_col[EE];
__device__ int   g_cnt[NN];
__device__ int   g_cur[NN];
__device__ int   g_off[NN + 1];
__device__ int   g_src[EE];
__device__ float g_w[EE];            // raw ew after fill

__device__ __align__(16) __half g_aggx_h[(size_t)NN * 64];
__device__ __align__(16) __half g_aggx_l[(size_t)NN * 64];
__device__ __align__(16) __half g_W1t_h[512 * 64];
__device__ __align__(16) __half g_W1t_l[512 * 64];
__device__ __align__(16) float  g_h1[(size_t)NN * HID];
__device__ __align__(16) __half g_W2t_h[512 * 512];
__device__ __align__(16) __half g_W2t_l[512 * 512];
__device__ __align__(16) __half g_agg1[(size_t)NN * HID];          // fp16 only (2-pass A)
__device__ __align__(16) __half g_xcat[(size_t)BGR * KP0];         // fp16 only (2-pass A)
__device__ __align__(16) __half g_Wf0t_h[(size_t)512 * KP0];
__device__ __align__(16) __half g_Wf0t_l[(size_t)512 * KP0];
__device__ __align__(16) float  g_t0f[BGR * HID];
__device__ __align__(16) __half g_t0_h[BGR * HID];
__device__ __align__(16) __half g_t0_l[BGR * HID];
__device__ __align__(16) __half g_Wf1t_h[512 * 512];
__device__ __align__(16) __half g_Wf1t_l[512 * 512];
__device__ __align__(16) __half g_t1_h[BGR * HID];
__device__ __align__(16) __half g_t1_l[BGR * HID];
__device__ __align__(16) __half g_Wf2t_h[512 * 512];
__device__ __align__(16) __half g_Wf2t_l[512 * 512];
__device__ __align__(16) float  g_t2[BGR * HID];

// ---------------- helpers ----------------
__device__ __forceinline__ uint32_t smem_u32(const void* p) {
    uint32_t a;
    asm("{ .reg .u64 t; cvta.to.shared.u64 t, %1; cvt.u32.u64 %0, t; }" : "=r"(a) : "l"(p));
    return a;
}
__device__ __forceinline__ void ldsm4(uint32_t* r, uint32_t addr) {
    asm volatile("ldmatrix.sync.aligned.m8n8.x4.shared.b16 {%0,%1,%2,%3}, [%4];"
        : "=r"(r[0]), "=r"(r[1]), "=r"(r[2]), "=r"(r[3]) : "r"(addr));
}
__device__ __forceinline__ void mma16816(float* d, const uint32_t* a, uint32_t b0, uint32_t b1) {
    asm volatile("mma.sync.aligned.m16n8k16.row.col.f32.f16.f16.f32 "
        "{%0,%1,%2,%3}, {%4,%5,%6,%7}, {%8,%9}, {%0,%1,%2,%3};"
        : "+f"(d[0]), "+f"(d[1]), "+f"(d[2]), "+f"(d[3])
        : "r"(a[0]), "r"(a[1]), "r"(a[2]), "r"(a[3]), "r"(b0), "r"(b1));
}
#define CP16(d, s)   asm volatile("cp.async.cg.shared.global [%0], [%1], 16;" :: "r"(d), "l"(s))
#define CP_COMMIT()  asm volatile("cp.async.commit_group;" ::: "memory")
#define CP_WAIT0()   asm volatile("cp.async.wait_group 0;" ::: "memory")
#define CP_WAIT1()   asm volatile("cp.async.wait_group 1;" ::: "memory")

__device__ __forceinline__ float lrelu(float v) { return v > 0.f ? v : 0.01f * v; }
__device__ __forceinline__ void split_h(float v, __half& h, __half& l) {
    h = __float2half(v);
    l = __float2half(v - __half2float(h));
}

// ---------------- setup ----------------
__global__ void k_setup(const int* ei) {
    int i = blockIdx.x * blockDim.x + threadIdx.x;
    if (i < NN) { g_cnt[i] = 0; g_cur[i] = 0; }
    if (i == 0) {
        int f = 1;
        for (int j = 0; j < 64; j++)
            if (ei[2 * j + 1] != 0) { f = 0; break; }
        g_flag = f;
    }
}
__global__ void k_edges(const void* ei) {
    int e = blockIdx.x * blockDim.x + threadIdx.x;
    if (e >= EE) return;
    int r, c;
    if (g_flag) {
        const long long* p = (const long long*)ei;
        r = (int)p[e]; c = (int)p[EE + e];
    } else {
        const int* p = (const int*)ei;
        r = p[e]; c = p[EE + e];
    }
    g_row[e] = r; g_col[e] = c;
    atomicAdd(&g_cnt[c], 1);
}
__global__ void k_scan() {
    __shared__ int sh[1024];
    int t = threadIdx.x;
    int base = t * 22;
    int local[22];
    int s = 0;
    #pragma unroll
    for (int i = 0; i < 22; i++) { local[i] = g_cnt[base + i]; s += local[i]; }
    sh[t] = s;
    __syncthreads();
    for (int off = 1; off < 1024; off <<= 1) {
        int v = (t >= off) ? sh[t - off] : 0;
        __syncthreads();
        sh[t] += v;
        __syncthreads();
    }
    int pre = (t == 0) ? 0 : sh[t - 1];
    #pragma unroll
    for (int i = 0; i < 22; i++) { g_off[base + i] = pre; pre += local[i]; }
    if (t == 0) g_off[NN] = EE;
}
__global__ void k_fill(const float* __restrict__ ew) {
    int e = blockIdx.x * blockDim.x + threadIdx.x;
    if (e >= EE) return;
    int c = g_col[e];
    int p = g_off[c] + atomicAdd(&g_cur[c], 1);
    g_src[p] = g_row[e];
    g_w[p] = ew[e];
}
__global__ void k_dis2() {
    int n = blockIdx.x * blockDim.x + threadIdx.x;
    if (n >= NN) return;
    float s = 1.0f;
    int a = g_off[n], b = g_off[n + 1];
    for (int p = a; p < b; p++) s += g_w[p];
    g_dis[n] = rsqrtf(s);
}

// ---------------- CSR gathers ----------------
__global__ void k_gather1(const float* __restrict__ x) {
    int n = blockIdx.x;
    int f = threadIdx.x;               // 64
    float dn = g_dis[n];
    float acc = 0.f;
    if (f < FEA) acc = dn * x[(size_t)n * FEA + f];
    int s = g_off[n], e = g_off[n + 1];
    for (int p = s; p < e; p++) {
        int src = g_src[p];
        float w = g_w[p] * g_dis[src];
        if (f < FEA) acc += x[(size_t)src * FEA + f] * w;
    }
    acc *= dn;
    if (f >= FEA) acc = 0.f;
    __half h, l;
    split_h(acc, h, l);
    g_aggx_h[(size_t)n * 64 + f] = h;
    g_aggx_l[(size_t)n * 64 + f] = l;
}

// conv2 A operand: fp16 rounding only (2-pass GEMM carries weight lo)
__global__ void k_gather2() {
    int n = blockIdx.x;
    int f4 = threadIdx.x;              // 128 threads, float4 each
    float dn = g_dis[n];
    float4 acc = ((const float4*)(g_h1 + (size_t)n * HID))[f4];
    acc.x *= dn; acc.y *= dn; acc.z *= dn; acc.w *= dn;
    int s = g_off[n], e = g_off[n + 1];
    for (int p = s; p < e; p++) {
        int src = g_src[p];
        float w = g_w[p] * g_dis[src];
        float4 v = ((const float4*)(g_h1 + (size_t)src * HID))[f4];
        acc.x += v.x * w; acc.y += v.y * w;
        acc.z += v.z * w; acc.w += v.w * w;
    }
    acc.x *= dn; acc.y *= dn; acc.z *= dn; acc.w *= dn;
    size_t o = (size_t)n * HID + f4 * 4;
    *(__half2*)&g_agg1[o]     = __halves2half2(__float2half(acc.x), __float2half(acc.y));
    *(__half2*)&g_agg1[o + 2] = __halves2half2(__float2half(acc.z), __float2half(acc.w));
}

// ---------------- weight transpose + split ----------------
__global__ void k_wtrans(const float* __restrict__ W, int K, int Kpad,
                         __half* __restrict__ oh, __half* __restrict__ ol) {
    __shared__ float tile[32][33];
    int kb = blockIdx.x * 32, nb = blockIdx.y * 32;
    int tx = threadIdx.x, ty = threadIdx.y;   // 32 x 8
    #pragma unroll
    for (int i = 0; i < 4; i++) {
        int row = kb + ty + i * 8;
        tile[ty + i * 8][tx] = (row < K) ? W[(size_t)row * 512 + nb + tx] : 0.f;
    }
    __syncthreads();
    #pragma unroll
    for (int i = 0; i < 4; i++) {
        int n = nb + ty + i * 8;
        int k = kb + tx;
        float v = tile[tx][ty + i * 8];
        __half h, l;
        split_h(v, h, l);
        oh[(size_t)n * Kpad + k] = h;
        ol[(size_t)n * Kpad + k] = l;
    }
}
__global__ void k_wtrans3(const float* __restrict__ Wa, const float* __restrict__ Wb,
                          const float* __restrict__ Wc,
                          __half* __restrict__ oha, __half* __restrict__ ola,
                          __half* __restrict__ ohb, __half* __restrict__ olb,
                          __half* __restrict__ ohc, __half* __restrict__ olc) {
    __shared__ float tile[32][33];
    const float* W = (blockIdx.z == 0) ? Wa : (blockIdx.z == 1) ? Wb : Wc;
    __half* oh = (blockIdx.z == 0) ? oha : (blockIdx.z == 1) ? ohb : ohc;
    __half* ol = (blockIdx.z == 0) ? ola : (blockIdx.z == 1) ? olb : olc;
    int kb = blockIdx.x * 32, nb = blockIdx.y * 32;
    int tx = threadIdx.x, ty = threadIdx.y;
    #pragma unroll
    for (int i = 0; i < 4; i++)
        tile[ty + i * 8][tx] = W[(size_t)(kb + ty + i * 8) * 512 + nb + tx];
    __syncthreads();
    #pragma unroll
    for (int i = 0; i < 4; i++) {
        int n = nb + ty + i * 8;
        int k = kb + tx;
        float v = tile[tx][ty + i * 8];
        __half h, l;
        split_h(v, h, l);
        oh[(size_t)n * 512 + k] = h;
        ol[(size_t)n * 512 + k] = l;
    }
}

// copy raw x into xcat (fp16) + zero pad cols
__global__ void k_copyx(const float* __restrict__ x) {
    int t = blockIdx.x * blockDim.x + threadIdx.x;
    if (t < NN * FEA) {
        int n = t / FEA, f = t - n * FEA;
        int b = n / MA, j = n - b * MA;
        g_xcat[(size_t)b * KP0 + j * CAT + HID + f] = __float2half(x[t]);
    } else if (t < NN * FEA + BGR * 24) {
        int t2 = t - NN * FEA;
        int b = t2 / 24, f = t2 - b * 24;
        g_xcat[(size_t)b * KP0 + FLAT + f] = __float2half(0.f);
    }
}
__global__ void k_zero_t0f() {
    int t = blockIdx.x * blockDim.x + threadIdx.x;
    if (t < BGR * HID) g_t0f[t] = 0.f;
}
__global__ void k_fin_t0(const float* __restrict__ bias) {
    int t = blockIdx.x * blockDim.x + threadIdx.x;
    if (t >= BGR * HID) return;
    int c = t & 511;
    float v = lrelu(g_t0f[t] + bias[c]);
    __half h, l;
    split_h(v, h, l);
    g_t0_h[t] = h;
    g_t0_l[t] = l;
}

// ================= 128x128 mma GEMM, 3-stage cp.async =================
// NP=3: full split (Ah,Al,Bh,Bl -> 3 passes). NP=2: A fp16-only (Ah,Bh,Bl -> 2 passes).
// EPI: 0 fp32+bias+lrelu, 2 xcat-scatter fp16, 3 atomicAdd raw fp32.
template <int EPI, int NP>
__global__ void __launch_bounds__(256, 1)
k_mma_gemm(const __half* __restrict__ Ah, const __half* __restrict__ Al, int lda,
           const __half* __restrict__ Bh, const __half* __restrict__ Bl, int ldb,
           const float* __restrict__ bias,
           float* __restrict__ Cf, __half* __restrict__ Ch,
           int ldc, int nch, int cper)
{
    constexpr uint32_t OFF_AL = 18432u;                            // NP==3 only
    constexpr uint32_t OFF_BH = (NP == 3) ? 36864u : 18432u;
    constexpr uint32_t OFF_BL = OFF_BH + 18432u;
    constexpr uint32_t BUFSZ  = OFF_BL + 18432u;                   // 73728 / 55296
    extern __shared__ char smx[];
    const uint32_t smb = smem_u32(smx);
    const int tid = threadIdx.x;
    const int wid = tid >> 5, lane = tid & 31;
    const int wm = wid & 1, wn = wid >> 1;
    const int row0 = blockIdx.y * 128, col0 = blockIdx.x * 128;
    const int c0 = blockIdx.z * cper;
    const int nc = min(nch, c0 + cper) - c0;

    const __half* pAh = Ah + (size_t)row0 * lda;
    const __half* pAl = (NP == 3) ? (Al + (size_t)row0 * lda) : nullptr;
    const __half* pBh = Bh + (size_t)col0 * ldb;
    const __half* pBl = Bl + (size_t)col0 * ldb;

    auto fill = [&](int b, int c) {
        const int kb = c * 64;
        uint32_t base = smb + b * BUFSZ;
        #pragma unroll
        for (int i = 0; i < 4; i++) {
            int idx = i * 256 + tid;
            int row = idx >> 3, seg = idx & 7;
            uint32_t d = base + (uint32_t)(row * 144 + seg * 16);
            size_t sa = (size_t)row * lda + kb + seg * 8;
            size_t sb = (size_t)row * ldb + kb + seg * 8;
            CP16(d, pAh + sa);
            if (NP == 3) CP16(d + OFF_AL, pAl + sa);
            CP16(d + OFF_BH, pBh + sb);
            CP16(d + OFF_BL, pBl + sb);
        }
    };

    float acc[4][4][4];
    #pragma unroll
    for (int i = 0; i < 4; i++)
        #pragma unroll
        for (int j = 0; j < 4; j++)
            #pragma unroll
            for (int q = 0; q < 4; q++) acc[i][j][q] = 0.f;

    const int g2 = lane >> 3, rr = lane & 7;
    const uint32_t aoff = (uint32_t)((wm * 64 + (g2 & 1) * 8 + rr) * 144 + (g2 >> 1) * 16);
    const uint32_t boff = (uint32_t)((wn * 32 + (g2 >> 1) * 8 + rr) * 144 + (g2 & 1) * 16);

    fill(0, c0);
    CP_COMMIT();
    if (nc > 1) { fill(1, c0 + 1); CP_COMMIT(); }

    for (int ci = 0; ci < nc; ci++) {
        if (ci + 1 < nc) CP_WAIT1(); else CP_WAIT0();
        __syncthreads();
        if (ci + 2 < nc) { fill((ci + 2) % 3, c0 + ci + 2); CP_COMMIT(); }
        uint32_t base = smb + (uint32_t)(ci % 3) * BUFSZ;
        #pragma unroll
        for (int k16 = 0; k16 < 4; k16++) {
            uint32_t Af[4][4], Lf[4][4], Bf[2][4], Mf[2][4];
            #pragma unroll
            for (int mt = 0; mt < 4; mt++) {
                ldsm4(Af[mt], base + aoff + mt * 2304 + k16 * 32);
                if (NP == 3) ldsm4(Lf[mt], base + OFF_AL + aoff + mt * 2304 + k16 * 32);
            }
            #pragma unroll
            for (int nt2 = 0; nt2 < 2; nt2++) {
                ldsm4(Bf[nt2], base + OFF_BH + boff + nt2 * 2304 + k16 * 32);
                ldsm4(Mf[nt2], base + OFF_BL + boff + nt2 * 2304 + k16 * 32);
            }
            #pragma unroll
            for (int mt = 0; mt < 4; mt++)
                #pragma unroll
                for (int nt = 0; nt < 4; nt++) {
                    uint32_t bh0 = Bf[nt >> 1][(nt & 1) * 2], bh1 = Bf[nt >> 1][(nt & 1) * 2 + 1];
                    uint32_t bl0 = Mf[nt >> 1][(nt & 1) * 2], bl1 = Mf[nt >> 1][(nt & 1) * 2 + 1];
                    mma16816(acc[mt][nt], Af[mt], bh0, bh1);
                    mma16816(acc[mt][nt], Af[mt], bl0, bl1);
                    if (NP == 3) mma16816(acc[mt][nt], Lf[mt], bh0, bh1);
                }
        }
        __syncthreads();
    }

    const int g = lane >> 2, t = lane & 3;
    #pragma unroll
    for (int mt = 0; mt < 4; mt++) {
        const int ra = row0 + wm * 64 + mt * 16 + g;
        const int rb = ra + 8;
        size_t oa = 0, ob = 0;
        if (EPI == 2) {
            int bg = ra / MA, j = ra - bg * MA;
            oa = (size_t)bg * KP0 + (size_t)j * CAT;
            bg = rb / MA; j = rb - bg * MA;
            ob = (size_t)bg * KP0 + (size_t)j * CAT;
        }
        #pragma unroll
        for (int nt = 0; nt < 4; nt++) {
            const int c = col0 + wn * 32 + nt * 8 + t * 2;
            float* d = acc[mt][nt];
            if (EPI == 3) {
                atomicAdd(&Cf[(size_t)ra * ldc + c],     d[0]);
                atomicAdd(&Cf[(size_t)ra * ldc + c + 1], d[1]);
                atomicAdd(&Cf[(size_t)rb * ldc + c],     d[2]);
                atomicAdd(&Cf[(size_t)rb * ldc + c + 1], d[3]);
            } else {
                float2 bv = *(const float2*)&bias[c];
                float v00 = lrelu(d[0] + bv.x), v01 = lrelu(d[1] + bv.y);
                float v10 = lrelu(d[2] + bv.x), v11 = lrelu(d[3] + bv.y);
                if (EPI == 0) {
                    float2 oA = {v00, v01}, oB = {v10, v11};
                    *(float2*)&Cf[(size_t)ra * ldc + c] = oA;
                    *(float2*)&Cf[(size_t)rb * ldc + c] = oB;
                } else {   // EPI == 2: xcat scatter, fp16 only
                    *(__half2*)&Ch[oa + c] = __halves2half2(__float2half(v00), __float2half(v01));
                    *(__half2*)&Ch[ob + c] = __halves2half2(__float2half(v10), __float2half(v11));
                }
            }
        }
    }
}

// ================= 64x64 mma GEMM (f1/f2), 3-pass =================
#define B64_AL 9216u
#define B64_BH 18432u
#define B64_BL 27648u
#define BUF64  36864u

template <int EPI>
__global__ void __launch_bounds__(128, 2)
k_mma64(const __half* __restrict__ Ah, const __half* __restrict__ Al, int lda,
        const __half* __restrict__ Bh, const __half* __restrict__ Bl, int ldb,
        const float* __restrict__ bias,
        float* __restrict__ Cf, __half* __restrict__ Ch, __half* __restrict__ Cl,
        int ldc, int nc)
{
    extern __shared__ char smx[];
    const uint32_t smb = smem_u32(smx);
    const int tid = threadIdx.x;
    const int wid = tid >> 5, lane = tid & 31;
    const int wm = wid & 1, wn = wid >> 1;
    const int row0 = blockIdx.y * 64, col0 = blockIdx.x * 64;

    const __half* pAh = Ah + (size_t)row0 * lda;
    const __half* pAl = Al + (size_t)row0 * lda;
    const __half* pBh = Bh + (size_t)col0 * ldb;
    const __half* pBl = Bl + (size_t)col0 * ldb;

    auto fill = [&](int b, int c) {
        const int kb = c * 64;
        uint32_t base = smb + b * BUF64;
        #pragma unroll
        for (int i = 0; i < 4; i++) {
            int idx = i * 128 + tid;
            int row = idx >> 3, seg = idx & 7;
            uint32_t d = base + (uint32_t)(row * 144 + seg * 16);
            size_t sa = (size_t)row * lda + kb + seg * 8;
            size_t sb = (size_t)row * ldb + kb + seg * 8;
            CP16(d,          pAh + sa);
            CP16(d + B64_AL, pAl + sa);
            CP16(d + B64_BH, pBh + sb);
            CP16(d + B64_BL, pBl + sb);
        }
    };

    float acc[2][4][4];
    #pragma unroll
    for (int i = 0; i < 2; i++)
        #pragma unroll
        for (int j = 0; j < 4; j++)
            #pragma unroll
            for (int q = 0; q < 4; q++) acc[i][j][q] = 0.f;

    const int g2 = lane >> 3, rr = lane & 7;
    const uint32_t aoff = (uint32_t)((wm * 32 + (g2 & 1) * 8 + rr) * 144 + (g2 >> 1) * 16);
    const uint32_t boff = (uint32_t)((wn * 32 + (g2 >> 1) * 8 + rr) * 144 + (g2 & 1) * 16);

    fill(0, 0);
    CP_COMMIT();
    if (nc > 1) { fill(1, 1); CP_COMMIT(); }

    for (int ci = 0; ci < nc; ci++) {
        if (ci + 1 < nc) CP_WAIT1(); else CP_WAIT0();
        __syncthreads();
        if (ci + 2 < nc) { fill((ci + 2) % 3, ci + 2); CP_COMMIT(); }
        uint32_t base = smb + (uint32_t)(ci % 3) * BUF64;
        #pragma unroll
        for (int k16 = 0; k16 < 4; k16++) {
            uint32_t Af[2][4], Lf[2][4], Bf[2][4], Mf[2][4];
            #pragma unroll
            for (int mt = 0; mt < 2; mt++) {
                ldsm4(Af[mt], base + aoff + mt * 2304 + k16 * 32);
                ldsm4(Lf[mt], base + B64_AL + aoff + mt * 2304 + k16 * 32);
            }
            #pragma unroll
            for (int nt2 = 0; nt2 < 2; nt2++) {
                ldsm4(Bf[nt2], base + B64_BH + boff + nt2 * 2304 + k16 * 32);
                ldsm4(Mf[nt2], base + B64_BL + boff + nt2 * 2304 + k16 * 32);
            }
            #pragma unroll
            for (int mt = 0; mt < 2; mt++)
                #pragma unroll
                for (int nt = 0; nt < 4; nt++) {
                    uint32_t bh0 = Bf[nt >> 1][(nt & 1) * 2], bh1 = Bf[nt >> 1][(nt & 1) * 2 + 1];
                    uint32_t bl0 = Mf[nt >> 1][(nt & 1) * 2], bl1 = Mf[nt >> 1][(nt & 1) * 2 + 1];
                    mma16816(acc[mt][nt], Af[mt], bh0, bh1);
                    mma16816(acc[mt][nt], Af[mt], bl0, bl1);
                    mma16816(acc[mt][nt], Lf[mt], bh0, bh1);
                }
        }
        __syncthreads();
    }

    const int g = lane >> 2, t = lane & 3;
    #pragma unroll
    for (int mt = 0; mt < 2; mt++) {
        const int ra = row0 + wm * 32 + mt * 16 + g;
        const int rb = ra + 8;
        #pragma unroll
        for (int nt = 0; nt < 4; nt++) {
            const int c = col0 + wn * 32 + nt * 8 + t * 2;
            float* d = acc[mt][nt];
            float2 bv = *(const float2*)&bias[c];
            float v00 = lrelu(d[0] + bv.x), v01 = lrelu(d[1] + bv.y);
            float v10 = lrelu(d[2] + bv.x), v11 = lrelu(d[3] + bv.y);
            if (EPI == 0) {
                float2 oA = {v00, v01}, oB = {v10, v11};
                *(float2*)&Cf[(size_t)ra * ldc + c] = oA;
                *(float2*)&Cf[(size_t)rb * ldc + c] = oB;
            } else {
                __half h00, l00, h01, l01, h10, l10, h11, l11;
                split_h(v00, h00, l00);
                split_h(v01, h01, l01);
                split_h(v10, h10, l10);
                split_h(v11, h11, l11);
                *(__half2*)&Ch[(size_t)ra * ldc + c] = __halves2half2(h00, h01);
                *(__half2*)&Cl[(size_t)ra * ldc + c] = __halves2half2(l00, l01);
                *(__half2*)&Ch[(size_t)rb * ldc + c] = __halves2half2(h10, h11);
                *(__half2*)&Cl[(size_t)rb * ldc + c] = __halves2half2(l10, l11);
            }
        }
    }
}

// ---------------- final layer ----------------
__global__ void k_out(const float* __restrict__ A, const float* __restrict__ Wo,
                      const float* __restrict__ bo, float* __restrict__ out)
{
    int b = blockIdx.x;
    int w = threadIdx.x >> 5, lane = threadIdx.x & 31;
    const float* a = A + (size_t)b * HID;
    float s = 0.f;
    for (int k = lane; k < HID; k += 32)
        s += a[k] * Wo[k * OUTD + w];
    #pragma unroll
    for (int o = 16; o > 0; o >>= 1) s += __shfl_xor_sync(0xFFFFFFFFu, s, o);
    __shared__ float sl[OUTD];
    if (lane == 0) sl[w] = s + bo[w];
    __syncthreads();
    if (threadIdx.x == 0) {
        float m = sl[0];
        #pragma unroll
        for (int o = 1; o < OUTD; o++) m = fmaxf(m, sl[o]);
        float sum = 0.f;
        #pragma unroll
        for (int o = 0; o < OUTD; o++) sum += expf(sl[o] - m);
        float l = logf(sum);
        #pragma unroll
        for (int o = 0; o < OUTD; o++) out[b * OUTD + o] = sl[o] - m - l;
    }
}

// ---------------- launch ----------------
static inline int cdiv(int a, int b) { return (a + b - 1) / b; }

extern "C" void kernel_launch(void* const* d_in, const int* in_sizes, int n_in,
                              void* d_out, int out_size)
{
    const float* x   = (const float*)d_in[0];
    const void*  ei  = d_in[1];
    const float* ew  = (const float*)d_in[2];
    const float* W1  = (const float*)d_in[3];
    const float* b1  = (const float*)d_in[4];
    const float* W2  = (const float*)d_in[5];
    const float* b2  = (const float*)d_in[6];
    const float* Wf0 = (const float*)d_in[7];
    const float* bf0 = (const float*)d_in[8];
    const float* Wf1 = (const float*)d_in[9];
    const float* bf1 = (const float*)d_in[10];
    const float* Wf2 = (const float*)d_in[11];
    const float* bf2 = (const float*)d_in[12];
    const float* Wo  = (const float*)d_in[13];
    const float* bo  = (const float*)d_in[14];
    float* out = (float*)d_out;

    __half *aggxh, *aggxl, *W1th, *W1tl, *W2th, *W2tl, *agg1, *xcat;
    __half *Wf0th, *Wf0tl, *t0h, *t0l, *Wf1th, *Wf1tl, *t1h, *t1l, *Wf2th, *Wf2tl;
    float *h1, *t0f, *t2;
    cudaGetSymbolAddress((void**)&aggxh, g_aggx_h);
    cudaGetSymbolAddress((void**)&aggxl, g_aggx_l);
    cudaGetSymbolAddress((void**)&W1th,  g_W1t_h);
    cudaGetSymbolAddress((void**)&W1tl,  g_W1t_l);
    cudaGetSymbolAddress((void**)&W2th,  g_W2t_h);
    cudaGetSymbolAddress((void**)&W2tl,  g_W2t_l);
    cudaGetSymbolAddress((void**)&agg1,  g_agg1);
    cudaGetSymbolAddress((void**)&xcat,  g_xcat);
    cudaGetSymbolAddress((void**)&Wf0th, g_Wf0t_h);
    cudaGetSymbolAddress((void**)&Wf0tl, g_Wf0t_l);
    cudaGetSymbolAddress((void**)&t0h,   g_t0_h);
    cudaGetSymbolAddress((void**)&t0l,   g_t0_l);
    cudaGetSymbolAddress((void**)&Wf1th, g_Wf1t_h);
    cudaGetSymbolAddress((void**)&Wf1tl, g_Wf1t_l);
    cudaGetSymbolAddress((void**)&t1h,   g_t1_h);
    cudaGetSymbolAddress((void**)&t1l,   g_t1_l);
    cudaGetSymbolAddress((void**)&Wf2th, g_Wf2t_h);
    cudaGetSymbolAddress((void**)&Wf2tl, g_Wf2t_l);
    cudaGetSymbolAddress((void**)&h1,    g_h1);
    cudaGetSymbolAddress((void**)&t0f,   g_t0f);
    cudaGetSymbolAddress((void**)&t2,    g_t2);

    const int SMEM3  = 3 * 73728;   // 221184 (NP=3)
    const int SMEM2  = 3 * 55296;   // 165888 (NP=2)
    const int SMEM64 = 3 * (int)BUF64;
    cudaFuncSetAttribute(k_mma_gemm<0, 3>, cudaFuncAttributeMaxDynamicSharedMemorySize, SMEM3);
    cudaFuncSetAttribute(k_mma_gemm<2, 2>, cudaFuncAttributeMaxDynamicSharedMemorySize, SMEM2);
    cudaFuncSetAttribute(k_mma_gemm<3, 2>, cudaFuncAttributeMaxDynamicSharedMemorySize, SMEM2);
    cudaFuncSetAttribute(k_mma64<0>, cudaFuncAttributeMaxDynamicSharedMemorySize, SMEM64);
    cudaFuncSetAttribute(k_mma64<1>, cudaFuncAttributeMaxDynamicSharedMemorySize, SMEM64);

    const int TPB = 256;

    // CSR build (no deg atomics)
    k_setup<<<cdiv(NN, TPB), TPB>>>((const int*)ei);
    k_edges<<<cdiv(EE, TPB), TPB>>>(ei);
    k_scan<<<1, 1024>>>();
    k_fill<<<cdiv(EE, TPB), TPB>>>(ew);
    k_dis2<<<cdiv(NN, TPB), TPB>>>();

    // weight transposes + split conversion
    {
        dim3 blk(32, 8);
        k_wtrans<<<dim3(2, 16), blk>>>(W1, FEA, 64, W1th, W1tl);
        k_wtrans<<<dim3(KP0 / 32, 16), blk>>>(Wf0, FLAT, KP0, Wf0th, Wf0tl);
        k_wtrans3<<<dim3(16, 16, 3), blk>>>(W2, Wf1, Wf2,
                                            W2th, W2tl, Wf1th, Wf1tl, Wf2th, Wf2tl);
    }
    k_zero_t0f<<<cdiv(BGR * HID, TPB), TPB>>>();

    // conv1: 3-pass (full accuracy into h1)
    k_gather1<<<NN, 64>>>(x);
    k_mma_gemm<0, 3><<<dim3(4, 176, 1), 256, SMEM3>>>(
        aggxh, aggxl, 64, W1th, W1tl, 64, b1, h1, nullptr, HID, 1, 1);

    // conv2: 2-pass (A fp16-only), epilogue scatters fp16 into xcat
    k_gather2<<<NN, 128>>>();
    k_copyx<<<cdiv(NN * FEA + BGR * 24, TPB), TPB>>>(x);
    k_mma_gemm<2, 2><<<dim3(4, 176, 1), 256, SMEM2>>>(
        agg1, nullptr, HID, W2th, W2tl, HID, b2, nullptr, xcat, 0, 8, 8);

    // f0: 2-pass, split-K=8 fp32 atomic reduce, then bias+lrelu+split
    k_mma_gemm<3, 2><<<dim3(4, 8, 8), 256, SMEM2>>>(
        xcat, nullptr, KP0, Wf0th, Wf0tl, KP0, nullptr, t0f, nullptr, HID, NCH0, 25);
    k_fin_t0<<<cdiv(BGR * HID, TPB), TPB>>>(bf0);

    // f1, f2: 3-pass 64x64
    k_mma64<1><<<dim3(8, 16), 128, SMEM64>>>(
        t0h, t0l, HID, Wf1th, Wf1tl, HID, bf1, nullptr, t1h, t1l, HID, 8);
    k_mma64<0><<<dim3(8, 16), 128, SMEM64>>>(
        t1h, t1l, HID, Wf2th, Wf2tl, HID, bf2, t2, nullptr, nullptr, HID, 8);

    // output head + log_softmax
    k_out<<<BGR, 128>>>(t2, Wo, bo, out);
}

// round 13
// speedup vs baseline: 1.3407x; 1.0452x over previous
#include <cuda_runtime.h>
#include <cuda_fp16.h>
#include <cstdint>

#define NN   22528
#define EE   360448
#define FEA  60
#define HID  512
#define OUTD 4
#define MA   22
#define BGR  1024
#define CAT  572
#define FLAT 12584
#define KP0  12608
#define NCH0 197

// ---------------- device scratch ----------------
__device__ int   g_flag;
__device__ float g_dis[NN];
__device__ int   g_row[EE];
__device__ int   g_col[EE];
__device__ int   g_cnt[NN];
__device__ int   g_cur[NN];
__device__ int   g_off[NN + 1];
__device__ int   g_src[EE];
__device__ float g_w[EE];

__device__ __align__(16) __half g_aggx[(size_t)NN * 64];           // fp16 (2-pass A)
__device__ __align__(16) __half g_W1t_h[512 * 64];
__device__ __align__(16) __half g_W1t_l[512 * 64];
__device__ __align__(16) __half g_h1[(size_t)NN * HID];            // fp16 conv1 output
__device__ __align__(16) __half g_W2t_h[512 * 512];
__device__ __align__(16) __half g_W2t_l[512 * 512];
__device__ __align__(16) __half g_agg1[(size_t)NN * HID];
__device__ __align__(16) __half g_xcat[(size_t)BGR * KP0];
__device__ __align__(16) __half g_Wf0t_h[(size_t)512 * KP0];
__device__ __align__(16) __half g_Wf0t_l[(size_t)512 * KP0];
__device__ __align__(16) float  g_t0f[BGR * HID];
__device__ __align__(16) __half g_t0[BGR * HID];
__device__ __align__(16) __half g_Wf1t_h[512 * 512];
__device__ __align__(16) __half g_Wf1t_l[512 * 512];
__device__ __align__(16) __half g_t1[BGR * HID];
__device__ __align__(16) __half g_Wf2t_h[512 * 512];
__device__ __align__(16) __half g_Wf2t_l[512 * 512];
__device__ __align__(16) float  g_t2[BGR * HID];

// ---------------- helpers ----------------
__device__ __forceinline__ uint32_t smem_u32(const void* p) {
    uint32_t a;
    asm("{ .reg .u64 t; cvta.to.shared.u64 t, %1; cvt.u32.u64 %0, t; }" : "=r"(a) : "l"(p));
    return a;
}
__device__ __forceinline__ void ldsm4(uint32_t* r, uint32_t addr) {
    asm volatile("ldmatrix.sync.aligned.m8n8.x4.shared.b16 {%0,%1,%2,%3}, [%4];"
        : "=r"(r[0]), "=r"(r[1]), "=r"(r[2]), "=r"(r[3]) : "r"(addr));
}
__device__ __forceinline__ void mma16816(float* d, const uint32_t* a, uint32_t b0, uint32_t b1) {
    asm volatile("mma.sync.aligned.m16n8k16.row.col.f32.f16.f16.f32 "
        "{%0,%1,%2,%3}, {%4,%5,%6,%7}, {%8,%9}, {%0,%1,%2,%3};"
        : "+f"(d[0]), "+f"(d[1]), "+f"(d[2]), "+f"(d[3])
        : "r"(a[0]), "r"(a[1]), "r"(a[2]), "r"(a[3]), "r"(b0), "r"(b1));
}
#define CP16(d, s)   asm volatile("cp.async.cg.shared.global [%0], [%1], 16;" :: "r"(d), "l"(s))
#define CP_COMMIT()  asm volatile("cp.async.commit_group;" ::: "memory")
#define CP_WAIT0()   asm volatile("cp.async.wait_group 0;" ::: "memory")
#define CP_WAIT1()   asm volatile("cp.async.wait_group 1;" ::: "memory")

__device__ __forceinline__ float lrelu(float v) { return v > 0.f ? v : 0.01f * v; }
__device__ __forceinline__ void split_h(float v, __half& h, __half& l) {
    h = __float2half(v);
    l = __float2half(v - __half2float(h));
}

// ---------------- setup ----------------
__global__ void k_setup(const int* ei) {
    int i = blockIdx.x * blockDim.x + threadIdx.x;
    if (i < NN) { g_cnt[i] = 0; g_cur[i] = 0; }
    if (i == 0) {
        int f = 1;
        for (int j = 0; j < 64; j++)
            if (ei[2 * j + 1] != 0) { f = 0; break; }
        g_flag = f;
    }
}
__global__ void k_edges(const void* ei) {
    int e = blockIdx.x * blockDim.x + threadIdx.x;
    if (e >= EE) return;
    int r, c;
    if (g_flag) {
        const long long* p = (const long long*)ei;
        r = (int)p[e]; c = (int)p[EE + e];
    } else {
        const int* p = (const int*)ei;
        r = p[e]; c = p[EE + e];
    }
    g_row[e] = r; g_col[e] = c;
    atomicAdd(&g_cnt[c], 1);
}
__global__ void k_scan() {
    __shared__ int sh[1024];
    int t = threadIdx.x;
    int base = t * 22;
    int local[22];
    int s = 0;
    #pragma unroll
    for (int i = 0; i < 22; i++) { local[i] = g_cnt[base + i]; s += local[i]; }
    sh[t] = s;
    __syncthreads();
    for (int off = 1; off < 1024; off <<= 1) {
        int v = (t >= off) ? sh[t - off] : 0;
        __syncthreads();
        sh[t] += v;
        __syncthreads();
    }
    int pre = (t == 0) ? 0 : sh[t - 1];
    #pragma unroll
    for (int i = 0; i < 22; i++) { g_off[base + i] = pre; pre += local[i]; }
    if (t == 0) g_off[NN] = EE;
}
__global__ void k_fill(const float* __restrict__ ew) {
    int e = blockIdx.x * blockDim.x + threadIdx.x;
    if (e >= EE) return;
    int c = g_col[e];
    int p = g_off[c] + atomicAdd(&g_cur[c], 1);
    g_src[p] = g_row[e];
    g_w[p] = ew[e];
}
__global__ void k_dis2() {
    int n = blockIdx.x * blockDim.x + threadIdx.x;
    if (n >= NN) return;
    float s = 1.0f;
    int a = g_off[n], b = g_off[n + 1];
    for (int p = a; p < b; p++) s += g_w[p];
    g_dis[n] = rsqrtf(s);
}

// ---------------- CSR gathers ----------------
__global__ void k_gather1(const float* __restrict__ x) {
    int n = blockIdx.x;
    int f = threadIdx.x;               // 64
    float dn = g_dis[n];
    float acc = 0.f;
    if (f < FEA) acc = dn * x[(size_t)n * FEA + f];
    int s = g_off[n], e = g_off[n + 1];
    for (int p = s; p < e; p++) {
        int src = g_src[p];
        float w = g_w[p] * g_dis[src];
        if (f < FEA) acc += x[(size_t)src * FEA + f] * w;
    }
    acc *= dn;
    if (f >= FEA) acc = 0.f;
    g_aggx[(size_t)n * 64 + f] = __float2half(acc);
}

// gather over fp16 h1 (halved traffic): 128 threads, 4 halves each
__global__ void k_gather2() {
    int n = blockIdx.x;
    int t = threadIdx.x;               // 128
    float dn = g_dis[n];
    uint2 raw = ((const uint2*)(g_h1 + (size_t)n * HID))[t];
    __half2* ph = (__half2*)&raw;
    float2 a0 = __half22float2(ph[0]);
    float2 a1 = __half22float2(ph[1]);
    float acc0 = a0.x * dn, acc1 = a0.y * dn, acc2 = a1.x * dn, acc3 = a1.y * dn;
    int s = g_off[n], e = g_off[n + 1];
    for (int p = s; p < e; p++) {
        int src = g_src[p];
        float w = g_w[p] * g_dis[src];
        uint2 rv = ((const uint2*)(g_h1 + (size_t)src * HID))[t];
        __half2* pv = (__half2*)&rv;
        float2 v0 = __half22float2(pv[0]);
        float2 v1 = __half22float2(pv[1]);
        acc0 += v0.x * w; acc1 += v0.y * w;
        acc2 += v1.x * w; acc3 += v1.y * w;
    }
    acc0 *= dn; acc1 *= dn; acc2 *= dn; acc3 *= dn;
    size_t o = (size_t)n * HID + t * 4;
    *(__half2*)&g_agg1[o]     = __halves2half2(__float2half(acc0), __float2half(acc1));
    *(__half2*)&g_agg1[o + 2] = __halves2half2(__float2half(acc2), __float2half(acc3));
}

// ---------------- weight transpose + split ----------------
__global__ void k_wtrans(const float* __restrict__ W, int K, int Kpad,
                         __half* __restrict__ oh, __half* __restrict__ ol) {
    __shared__ float tile[32][33];
    int kb = blockIdx.x * 32, nb = blockIdx.y * 32;
    int tx = threadIdx.x, ty = threadIdx.y;   // 32 x 8
    #pragma unroll
    for (int i = 0; i < 4; i++) {
        int row = kb + ty + i * 8;
        tile[ty + i * 8][tx] = (row < K) ? W[(size_t)row * 512 + nb + tx] : 0.f;
    }
    __syncthreads();
    #pragma unroll
    for (int i = 0; i < 4; i++) {
        int n = nb + ty + i * 8;
        int k = kb + tx;
        float v = tile[tx][ty + i * 8];
        __half h, l;
        split_h(v, h, l);
        oh[(size_t)n * Kpad + k] = h;
        ol[(size_t)n * Kpad + k] = l;
    }
}
__global__ void k_wtrans3(const float* __restrict__ Wa, const float* __restrict__ Wb,
                          const float* __restrict__ Wc,
                          __half* __restrict__ oha, __half* __restrict__ ola,
                          __half* __restrict__ ohb, __half* __restrict__ olb,
                          __half* __restrict__ ohc, __half* __restrict__ olc) {
    __shared__ float tile[32][33];
    const float* W = (blockIdx.z == 0) ? Wa : (blockIdx.z == 1) ? Wb : Wc;
    __half* oh = (blockIdx.z == 0) ? oha : (blockIdx.z == 1) ? ohb : ohc;
    __half* ol = (blockIdx.z == 0) ? ola : (blockIdx.z == 1) ? olb : olc;
    int kb = blockIdx.x * 32, nb = blockIdx.y * 32;
    int tx = threadIdx.x, ty = threadIdx.y;
    #pragma unroll
    for (int i = 0; i < 4; i++)
        tile[ty + i * 8][tx] = W[(size_t)(kb + ty + i * 8) * 512 + nb + tx];
    __syncthreads();
    #pragma unroll
    for (int i = 0; i < 4; i++) {
        int n = nb + ty + i * 8;
        int k = kb + tx;
        float v = tile[tx][ty + i * 8];
        __half h, l;
        split_h(v, h, l);
        oh[(size_t)n * 512 + k] = h;
        ol[(size_t)n * 512 + k] = l;
    }
}

__global__ void k_copyx(const float* __restrict__ x) {
    int t = blockIdx.x * blockDim.x + threadIdx.x;
    if (t < NN * FEA) {
        int n = t / FEA, f = t - n * FEA;
        int b = n / MA, j = n - b * MA;
        g_xcat[(size_t)b * KP0 + j * CAT + HID + f] = __float2half(x[t]);
    } else if (t < NN * FEA + BGR * 24) {
        int t2 = t - NN * FEA;
        int b = t2 / 24, f = t2 - b * 24;
        g_xcat[(size_t)b * KP0 + FLAT + f] = __float2half(0.f);
    }
}
__global__ void k_zero_t0f() {
    int t = blockIdx.x * blockDim.x + threadIdx.x;
    if (t < BGR * HID) g_t0f[t] = 0.f;
}
__global__ void k_fin_t0(const float* __restrict__ bias) {
    int t = blockIdx.x * blockDim.x + threadIdx.x;
    if (t >= BGR * HID) return;
    int c = t & 511;
    g_t0[t] = __float2half(lrelu(g_t0f[t] + bias[c]));
}

// ================= 128x128 mma GEMM, 3-stage cp.async, 2-pass =================
// A fp16 single; B hi/lo. EPI: 2 xcat-scatter fp16, 3 atomicAdd raw fp32,
// 4 fp16 row store (bias+lrelu).
template <int EPI>
__global__ void __launch_bounds__(256, 1)
k_mma_gemm(const __half* __restrict__ Ah, int lda,
           const __half* __restrict__ Bh, const __half* __restrict__ Bl, int ldb,
           const float* __restrict__ bias,
           float* __restrict__ Cf, __half* __restrict__ Ch,
           int ldc, int nch, int cper)
{
    constexpr uint32_t OFF_BH = 18432u;
    constexpr uint32_t OFF_BL = 36864u;
    constexpr uint32_t BUFSZ  = 55296u;
    extern __shared__ char smx[];
    const uint32_t smb = smem_u32(smx);
    const int tid = threadIdx.x;
    const int wid = tid >> 5, lane = tid & 31;
    const int wm = wid & 1, wn = wid >> 1;
    const int row0 = blockIdx.y * 128, col0 = blockIdx.x * 128;
    const int c0 = blockIdx.z * cper;
    const int nc = min(nch, c0 + cper) - c0;

    const __half* pAh = Ah + (size_t)row0 * lda;
    const __half* pBh = Bh + (size_t)col0 * ldb;
    const __half* pBl = Bl + (size_t)col0 * ldb;

    auto fill = [&](int b, int c) {
        const int kb = c * 64;
        uint32_t base = smb + b * BUFSZ;
        #pragma unroll
        for (int i = 0; i < 4; i++) {
            int idx = i * 256 + tid;
            int row = idx >> 3, seg = idx & 7;
            uint32_t d = base + (uint32_t)(row * 144 + seg * 16);
            size_t sa = (size_t)row * lda + kb + seg * 8;
            size_t sb = (size_t)row * ldb + kb + seg * 8;
            CP16(d, pAh + sa);
            CP16(d + OFF_BH, pBh + sb);
            CP16(d + OFF_BL, pBl + sb);
        }
    };

    float acc[4][4][4];
    #pragma unroll
    for (int i = 0; i < 4; i++)
        #pragma unroll
        for (int j = 0; j < 4; j++)
            #pragma unroll
            for (int q = 0; q < 4; q++) acc[i][j][q] = 0.f;

    const int g2 = lane >> 3, rr = lane & 7;
    const uint32_t aoff = (uint32_t)((wm * 64 + (g2 & 1) * 8 + rr) * 144 + (g2 >> 1) * 16);
    const uint32_t boff = (uint32_t)((wn * 32 + (g2 >> 1) * 8 + rr) * 144 + (g2 & 1) * 16);

    fill(0, c0);
    CP_COMMIT();
    if (nc > 1) { fill(1, c0 + 1); CP_COMMIT(); }

    for (int ci = 0; ci < nc; ci++) {
        if (ci + 1 < nc) CP_WAIT1(); else CP_WAIT0();
        __syncthreads();
        if (ci + 2 < nc) { fill((ci + 2) % 3, c0 + ci + 2); CP_COMMIT(); }
        uint32_t base = smb + (uint32_t)(ci % 3) * BUFSZ;
        #pragma unroll
        for (int k16 = 0; k16 < 4; k16++) {
            uint32_t Af[4][4], Bf[2][4], Mf[2][4];
            #pragma unroll
            for (int mt = 0; mt < 4; mt++)
                ldsm4(Af[mt], base + aoff + mt * 2304 + k16 * 32);
            #pragma unroll
            for (int nt2 = 0; nt2 < 2; nt2++) {
                ldsm4(Bf[nt2], base + OFF_BH + boff + nt2 * 2304 + k16 * 32);
                ldsm4(Mf[nt2], base + OFF_BL + boff + nt2 * 2304 + k16 * 32);
            }
            #pragma unroll
            for (int mt = 0; mt < 4; mt++)
                #pragma unroll
                for (int nt = 0; nt < 4; nt++) {
                    uint32_t bh0 = Bf[nt >> 1][(nt & 1) * 2], bh1 = Bf[nt >> 1][(nt & 1) * 2 + 1];
                    uint32_t bl0 = Mf[nt >> 1][(nt & 1) * 2], bl1 = Mf[nt >> 1][(nt & 1) * 2 + 1];
                    mma16816(acc[mt][nt], Af[mt], bh0, bh1);
                    mma16816(acc[mt][nt], Af[mt], bl0, bl1);
                }
        }
        __syncthreads();
    }

    const int g = lane >> 2, t = lane & 3;
    #pragma unroll
    for (int mt = 0; mt < 4; mt++) {
        const int ra = row0 + wm * 64 + mt * 16 + g;
        const int rb = ra + 8;
        size_t oa = 0, ob = 0;
        if (EPI == 2) {
            int bg = ra / MA, j = ra - bg * MA;
            oa = (size_t)bg * KP0 + (size_t)j * CAT;
            bg = rb / MA; j = rb - bg * MA;
            ob = (size_t)bg * KP0 + (size_t)j * CAT;
        }
        #pragma unroll
        for (int nt = 0; nt < 4; nt++) {
            const int c = col0 + wn * 32 + nt * 8 + t * 2;
            float* d = acc[mt][nt];
            if (EPI == 3) {
                atomicAdd(&Cf[(size_t)ra * ldc + c],     d[0]);
                atomicAdd(&Cf[(size_t)ra * ldc + c + 1], d[1]);
                atomicAdd(&Cf[(size_t)rb * ldc + c],     d[2]);
                atomicAdd(&Cf[(size_t)rb * ldc + c + 1], d[3]);
            } else {
                float2 bv = *(const float2*)&bias[c];
                float v00 = lrelu(d[0] + bv.x), v01 = lrelu(d[1] + bv.y);
                float v10 = lrelu(d[2] + bv.x), v11 = lrelu(d[3] + bv.y);
                size_t pa = (EPI == 2) ? (oa + c) : ((size_t)ra * ldc + c);
                size_t pb = (EPI == 2) ? (ob + c) : ((size_t)rb * ldc + c);
                *(__half2*)&Ch[pa] = __halves2half2(__float2half(v00), __float2half(v01));
                *(__half2*)&Ch[pb] = __halves2half2(__float2half(v10), __float2half(v11));
            }
        }
    }
}

// ================= 64x64 mma GEMM (f1/f2), 2-pass =================
#define B64_BH 9216u
#define B64_BL 18432u
#define BUF64  27648u

template <int EPI>   // 0 fp32 out, 1 fp16 out
__global__ void __launch_bounds__(128, 2)
k_mma64(const __half* __restrict__ Ah, int lda,
        const __half* __restrict__ Bh, const __half* __restrict__ Bl, int ldb,
        const float* __restrict__ bias,
        float* __restrict__ Cf, __half* __restrict__ Ch,
        int ldc, int nc)
{
    extern __shared__ char smx[];
    const uint32_t smb = smem_u32(smx);
    const int tid = threadIdx.x;
    const int wid = tid >> 5, lane = tid & 31;
    const int wm = wid & 1, wn = wid >> 1;
    const int row0 = blockIdx.y * 64, col0 = blockIdx.x * 64;

    const __half* pAh = Ah + (size_t)row0 * lda;
    const __half* pBh = Bh + (size_t)col0 * ldb;
    const __half* pBl = Bl + (size_t)col0 * ldb;

    auto fill = [&](int b, int c) {
        const int kb = c * 64;
        uint32_t base = smb + b * BUF64;
        #pragma unroll
        for (int i = 0; i < 4; i++) {
            int idx = i * 128 + tid;
            int row = idx >> 3, seg = idx & 7;
            uint32_t d = base + (uint32_t)(row * 144 + seg * 16);
            size_t sa = (size_t)row * lda + kb + seg * 8;
            size_t sb = (size_t)row * ldb + kb + seg * 8;
            CP16(d,          pAh + sa);
            CP16(d + B64_BH, pBh + sb);
            CP16(d + B64_BL, pBl + sb);
        }
    };

    float acc[2][4][4];
    #pragma unroll
    for (int i = 0; i < 2; i++)
        #pragma unroll
        for (int j = 0; j < 4; j++)
            #pragma unroll
            for (int q = 0; q < 4; q++) acc[i][j][q] = 0.f;

    const int g2 = lane >> 3, rr = lane & 7;
    const uint32_t aoff = (uint32_t)((wm * 32 + (g2 & 1) * 8 + rr) * 144 + (g2 >> 1) * 16);
    const uint32_t boff = (uint32_t)((wn * 32 + (g2 >> 1) * 8 + rr) * 144 + (g2 & 1) * 16);

    fill(0, 0);
    CP_COMMIT();
    if (nc > 1) { fill(1, 1); CP_COMMIT(); }

    for (int ci = 0; ci < nc; ci++) {
        if (ci + 1 < nc) CP_WAIT1(); else CP_WAIT0();
        __syncthreads();
        if (ci + 2 < nc) { fill((ci + 2) % 3, ci + 2); CP_COMMIT(); }
        uint32_t base = smb + (uint32_t)(ci % 3) * BUF64;
        #pragma unroll
        for (int k16 = 0; k16 < 4; k16++) {
            uint32_t Af[2][4], Bf[2][4], Mf[2][4];
            #pragma unroll
            for (int mt = 0; mt < 2; mt++)
                ldsm4(Af[mt], base + aoff + mt * 2304 + k16 * 32);
            #pragma unroll
            for (int nt2 = 0; nt2 < 2; nt2++) {
                ldsm4(Bf[nt2], base + B64_BH + boff + nt2 * 2304 + k16 * 32);
                ldsm4(Mf[nt2], base + B64_BL + boff + nt2 * 2304 + k16 * 32);
            }
            #pragma unroll
            for (int mt = 0; mt < 2; mt++)
                #pragma unroll
                for (int nt = 0; nt < 4; nt++) {
                    uint32_t bh0 = Bf[nt >> 1][(nt & 1) * 2], bh1 = Bf[nt >> 1][(nt & 1) * 2 + 1];
                    uint32_t bl0 = Mf[nt >> 1][(nt & 1) * 2], bl1 = Mf[nt >> 1][(nt & 1) * 2 + 1];
                    mma16816(acc[mt][nt], Af[mt], bh0, bh1);
                    mma16816(acc[mt][nt], Af[mt], bl0, bl1);
                }
        }
        __syncthreads();
    }

    const int g = lane >> 2, t = lane & 3;
    #pragma unroll
    for (int mt = 0; mt < 2; mt++) {
        const int ra = row0 + wm * 32 + mt * 16 + g;
        const int rb = ra + 8;
        #pragma unroll
        for (int nt = 0; nt < 4; nt++) {
            const int c = col0 + wn * 32 + nt * 8 + t * 2;
            float* d = acc[mt][nt];
            float2 bv = *(const float2*)&bias[c];
            float v00 = lrelu(d[0] + bv.x), v01 = lrelu(d[1] + bv.y);
            float v10 = lrelu(d[2] + bv.x), v11 = lrelu(d[3] + bv.y);
            if (EPI == 0) {
                float2 oA = {v00, v01}, oB = {v10, v11};
                *(float2*)&Cf[(size_t)ra * ldc + c] = oA;
                *(float2*)&Cf[(size_t)rb * ldc + c] = oB;
            } else {
                *(__half2*)&Ch[(size_t)ra * ldc + c] = __halves2half2(__float2half(v00), __float2half(v01));
                *(__half2*)&Ch[(size_t)rb * ldc + c] = __halves2half2(__float2half(v10), __float2half(v11));
            }
        }
    }
}

// ---------------- final layer ----------------
__global__ void k_out(const float* __restrict__ A, const float* __restrict__ Wo,
                      const float* __restrict__ bo, float* __restrict__ out)
{
    int b = blockIdx.x;
    int w = threadIdx.x >> 5, lane = threadIdx.x & 31;
    const float* a = A + (size_t)b * HID;
    float s = 0.f;
    for (int k = lane; k < HID; k += 32)
        s += a[k] * Wo[k * OUTD + w];
    #pragma unroll
    for (int o = 16; o > 0; o >>= 1) s += __shfl_xor_sync(0xFFFFFFFFu, s, o);
    __shared__ float sl[OUTD];
    if (lane == 0) sl[w] = s + bo[w];
    __syncthreads();
    if (threadIdx.x == 0) {
        float m = sl[0];
        #pragma unroll
        for (int o = 1; o < OUTD; o++) m = fmaxf(m, sl[o]);
        float sum = 0.f;
        #pragma unroll
        for (int o = 0; o < OUTD; o++) sum += expf(sl[o] - m);
        float l = logf(sum);
        #pragma unroll
        for (int o = 0; o < OUTD; o++) out[b * OUTD + o] = sl[o] - m - l;
    }
}

// ---------------- launch ----------------
static inline int cdiv(int a, int b) { return (a + b - 1) / b; }

extern "C" void kernel_launch(void* const* d_in, const int* in_sizes, int n_in,
                              void* d_out, int out_size)
{
    const float* x   = (const float*)d_in[0];
    const void*  ei  = d_in[1];
    const float* ew  = (const float*)d_in[2];
    const float* W1  = (const float*)d_in[3];
    const float* b1  = (const float*)d_in[4];
    const float* W2  = (const float*)d_in[5];
    const float* b2  = (const float*)d_in[6];
    const float* Wf0 = (const float*)d_in[7];
    const float* bf0 = (const float*)d_in[8];
    const float* Wf1 = (const float*)d_in[9];
    const float* bf1 = (const float*)d_in[10];
    const float* Wf2 = (const float*)d_in[11];
    const float* bf2 = (const float*)d_in[12];
    const float* Wo  = (const float*)d_in[13];
    const float* bo  = (const float*)d_in[14];
    float* out = (float*)d_out;

    __half *aggx, *W1th, *W1tl, *W2th, *W2tl, *h1, *agg1, *xcat;
    __half *Wf0th, *Wf0tl, *t0, *Wf1th, *Wf1tl, *t1, *Wf2th, *Wf2tl;
    float *t0f, *t2;
    cudaGetSymbolAddress((void**)&aggx,  g_aggx);
    cudaGetSymbolAddress((void**)&W1th,  g_W1t_h);
    cudaGetSymbolAddress((void**)&W1tl,  g_W1t_l);
    cudaGetSymbolAddress((void**)&W2th,  g_W2t_h);
    cudaGetSymbolAddress((void**)&W2tl,  g_W2t_l);
    cudaGetSymbolAddress((void**)&h1,    g_h1);
    cudaGetSymbolAddress((void**)&agg1,  g_agg1);
    cudaGetSymbolAddress((void**)&xcat,  g_xcat);
    cudaGetSymbolAddress((void**)&Wf0th, g_Wf0t_h);
    cudaGetSymbolAddress((void**)&Wf0tl, g_Wf0t_l);
    cudaGetSymbolAddress((void**)&t0,    g_t0);
    cudaGetSymbolAddress((void**)&Wf1th, g_Wf1t_h);
    cudaGetSymbolAddress((void**)&Wf1tl, g_Wf1t_l);
    cudaGetSymbolAddress((void**)&t1,    g_t1);
    cudaGetSymbolAddress((void**)&Wf2th, g_Wf2t_h);
    cudaGetSymbolAddress((void**)&Wf2tl, g_Wf2t_l);
    cudaGetSymbolAddress((void**)&t0f,   g_t0f);
    cudaGetSymbolAddress((void**)&t2,    g_t2);

    const int SMEM2  = 3 * 55296;   // 165888
    const int SMEM64 = 3 * (int)BUF64;   // 82944
    cudaFuncSetAttribute(k_mma_gemm<2>, cudaFuncAttributeMaxDynamicSharedMemorySize, SMEM2);
    cudaFuncSetAttribute(k_mma_gemm<3>, cudaFuncAttributeMaxDynamicSharedMemorySize, SMEM2);
    cudaFuncSetAttribute(k_mma_gemm<4>, cudaFuncAttributeMaxDynamicSharedMemorySize, SMEM2);
    cudaFuncSetAttribute(k_mma64<0>, cudaFuncAttributeMaxDynamicSharedMemorySize, SMEM64);
    cudaFuncSetAttribute(k_mma64<1>, cudaFuncAttributeMaxDynamicSharedMemorySize, SMEM64);

    const int TPB = 256;

    // CSR build (no deg atomics)
    k_setup<<<cdiv(NN, TPB), TPB>>>((const int*)ei);
    k_edges<<<cdiv(EE, TPB), TPB>>>(ei);
    k_scan<<<1, 1024>>>();
    k_fill<<<cdiv(EE, TPB), TPB>>>(ew);
    k_dis2<<<cdiv(NN, TPB), TPB>>>();

    // weight transposes + split conversion
    {
        dim3 blk(32, 8);
        k_wtrans<<<dim3(2, 16), blk>>>(W1, FEA, 64, W1th, W1tl);
        k_wtrans<<<dim3(KP0 / 32, 16), blk>>>(Wf0, FLAT, KP0, Wf0th, Wf0tl);
        k_wtrans3<<<dim3(16, 16, 3), blk>>>(W2, Wf1, Wf2,
                                            W2th, W2tl, Wf1th, Wf1tl, Wf2th, Wf2tl);
    }
    k_zero_t0f<<<cdiv(BGR * HID, TPB), TPB>>>();

    // conv1: 2-pass, fp16 output h1
    k_gather1<<<NN, 64>>>(x);
    k_mma_gemm<4><<<dim3(4, 176, 1), 256, SMEM2>>>(
        aggx, 64, W1th, W1tl, 64, b1, nullptr, h1, HID, 1, 1);

    // conv2: 2-pass over fp16 agg1, epilogue scatters fp16 into xcat
    k_gather2<<<NN, 128>>>();
    k_copyx<<<cdiv(NN * FEA + BGR * 24, TPB), TPB>>>(x);
    k_mma_gemm<2><<<dim3(4, 176, 1), 256, SMEM2>>>(
        agg1, HID, W2th, W2tl, HID, b2, nullptr, xcat, 0, 8, 8);

    // f0: 2-pass, split-K=8 fp32 atomic reduce, then bias+lrelu -> fp16 t0
    k_mma_gemm<3><<<dim3(4, 8, 8), 256, SMEM2>>>(
        xcat, KP0, Wf0th, Wf0tl, KP0, nullptr, t0f, nullptr, HID, NCH0, 25);
    k_fin_t0<<<cdiv(BGR * HID, TPB), TPB>>>(bf0);

    // f1, f2: 2-pass 64x64
    k_mma64<1><<<dim3(8, 16), 128, SMEM64>>>(
        t0, HID, Wf1th, Wf1tl, HID, bf1, nullptr, t1, HID, 8);
    k_mma64<0><<<dim3(8, 16), 128, SMEM64>>>(
        t1, HID, Wf2th, Wf2tl, HID, bf2, t2, nullptr, HID, 8);

    // output head + log_softmax
    k_out<<<BGR, 128>>>(t2, Wo, bo, out);
}

// round 14
// speedup vs baseline: 1.8128x; 1.3521x over previous
#include <cuda_runtime.h>
#include <cuda_fp16.h>
#include <cstdint>

#define NN   22528
#define EE   360448
#define FEA  60
#define HID  512
#define OUTD 4
#define MA   22
#define BGR  1024
#define CAT  572
#define FLAT 12584
#define KP0  12608
#define NCH0 197

// ---------------- device scratch ----------------
__device__ int   g_flag;
__device__ float g_dis[NN];
__device__ int   g_row[EE];
__device__ int   g_col[EE];
__device__ int   g_cnt[NN];
__device__ int   g_cur[NN];
__device__ int   g_off[NN + 1];
__device__ int   g_src[EE];
__device__ float g_w[EE];

__device__ __align__(16) __half g_aggx[(size_t)NN * 64];
__device__ __align__(16) __half g_W1t[512 * 64];
__device__ __align__(16) __half g_h1[(size_t)NN * HID];
__device__ __align__(16) __half g_W2t[512 * 512];
__device__ __align__(16) __half g_agg1[(size_t)NN * HID];
__device__ __align__(16) __half g_xcat[(size_t)BGR * KP0];
__device__ __align__(16) __half g_Wf0t[(size_t)512 * KP0];
__device__ __align__(16) float  g_t0f[BGR * HID];
__device__ __align__(16) __half g_t0[BGR * HID];
__device__ __align__(16) __half g_Wf1t[512 * 512];
__device__ __align__(16) __half g_t1[BGR * HID];
__device__ __align__(16) __half g_Wf2t[512 * 512];
__device__ __align__(16) float  g_t2[BGR * HID];

// ---------------- helpers ----------------
__device__ __forceinline__ uint32_t smem_u32(const void* p) {
    uint32_t a;
    asm("{ .reg .u64 t; cvta.to.shared.u64 t, %1; cvt.u32.u64 %0, t; }" : "=r"(a) : "l"(p));
    return a;
}
__device__ __forceinline__ void ldsm4(uint32_t* r, uint32_t addr) {
    asm volatile("ldmatrix.sync.aligned.m8n8.x4.shared.b16 {%0,%1,%2,%3}, [%4];"
        : "=r"(r[0]), "=r"(r[1]), "=r"(r[2]), "=r"(r[3]) : "r"(addr));
}
__device__ __forceinline__ void mma16816(float* d, const uint32_t* a, uint32_t b0, uint32_t b1) {
    asm volatile("mma.sync.aligned.m16n8k16.row.col.f32.f16.f16.f32 "
        "{%0,%1,%2,%3}, {%4,%5,%6,%7}, {%8,%9}, {%0,%1,%2,%3};"
        : "+f"(d[0]), "+f"(d[1]), "+f"(d[2]), "+f"(d[3])
        : "r"(a[0]), "r"(a[1]), "r"(a[2]), "r"(a[3]), "r"(b0), "r"(b1));
}
#define CP16(d, s)   asm volatile("cp.async.cg.shared.global [%0], [%1], 16;" :: "r"(d), "l"(s))
#define CP_COMMIT()  asm volatile("cp.async.commit_group;" ::: "memory")
#define CP_WAIT0()   asm volatile("cp.async.wait_group 0;" ::: "memory")
#define CP_WAIT1()   asm volatile("cp.async.wait_group 1;" ::: "memory")

__device__ __forceinline__ float lrelu(float v) { return v > 0.f ? v : 0.01f * v; }

// ---------------- setup ----------------
__global__ void k_setup(const int* ei) {
    int i = blockIdx.x * blockDim.x + threadIdx.x;
    if (i < NN) { g_cnt[i] = 0; g_cur[i] = 0; }
    if (i == 0) {
        int f = 1;
        for (int j = 0; j < 64; j++)
            if (ei[2 * j + 1] != 0) { f = 0; break; }
        g_flag = f;
    }
}
__global__ void k_edges(const void* ei) {
    int e = blockIdx.x * blockDim.x + threadIdx.x;
    if (e >= EE) return;
    int r, c;
    if (g_flag) {
        const long long* p = (const long long*)ei;
        r = (int)p[e]; c = (int)p[EE + e];
    } else {
        const int* p = (const int*)ei;
        r = p[e]; c = p[EE + e];
    }
    g_row[e] = r; g_col[e] = c;
    atomicAdd(&g_cnt[c], 1);
}
__global__ void k_scan() {
    __shared__ int sh[1024];
    int t = threadIdx.x;
    int base = t * 22;
    int local[22];
    int s = 0;
    #pragma unroll
    for (int i = 0; i < 22; i++) { local[i] = g_cnt[base + i]; s += local[i]; }
    sh[t] = s;
    __syncthreads();
    for (int off = 1; off < 1024; off <<= 1) {
        int v = (t >= off) ? sh[t - off] : 0;
        __syncthreads();
        sh[t] += v;
        __syncthreads();
    }
    int pre = (t == 0) ? 0 : sh[t - 1];
    #pragma unroll
    for (int i = 0; i < 22; i++) { g_off[base + i] = pre; pre += local[i]; }
    if (t == 0) g_off[NN] = EE;
}
__global__ void k_fill(const float* __restrict__ ew) {
    int e = blockIdx.x * blockDim.x + threadIdx.x;
    if (e >= EE) return;
    int c = g_col[e];
    int p = g_off[c] + atomicAdd(&g_cur[c], 1);
    g_src[p] = g_row[e];
    g_w[p] = ew[e];
}
__global__ void k_dis2() {
    int n = blockIdx.x * blockDim.x + threadIdx.x;
    if (n >= NN) return;
    float s = 1.0f;
    int a = g_off[n], b = g_off[n + 1];
    for (int p = a; p < b; p++) s += g_w[p];
    g_dis[n] = rsqrtf(s);
}

// ---------------- CSR gathers ----------------
__global__ void k_gather1(const float* __restrict__ x) {
    int n = blockIdx.x;
    int f = threadIdx.x;               // 64
    float dn = g_dis[n];
    float acc = 0.f;
    if (f < FEA) acc = dn * x[(size_t)n * FEA + f];
    int s = g_off[n], e = g_off[n + 1];
    for (int p = s; p < e; p++) {
        int src = g_src[p];
        float w = g_w[p] * g_dis[src];
        if (f < FEA) acc += x[(size_t)src * FEA + f] * w;
    }
    acc *= dn;
    if (f >= FEA) acc = 0.f;
    g_aggx[(size_t)n * 64 + f] = __float2half(acc);
}

__global__ void k_gather2() {
    int n = blockIdx.x;
    int t = threadIdx.x;               // 128
    float dn = g_dis[n];
    uint2 raw = ((const uint2*)(g_h1 + (size_t)n * HID))[t];
    __half2* ph = (__half2*)&raw;
    float2 a0 = __half22float2(ph[0]);
    float2 a1 = __half22float2(ph[1]);
    float acc0 = a0.x * dn, acc1 = a0.y * dn, acc2 = a1.x * dn, acc3 = a1.y * dn;
    int s = g_off[n], e = g_off[n + 1];
    for (int p = s; p < e; p++) {
        int src = g_src[p];
        float w = g_w[p] * g_dis[src];
        uint2 rv = ((const uint2*)(g_h1 + (size_t)src * HID))[t];
        __half2* pv = (__half2*)&rv;
        float2 v0 = __half22float2(pv[0]);
        float2 v1 = __half22float2(pv[1]);
        acc0 += v0.x * w; acc1 += v0.y * w;
        acc2 += v1.x * w; acc3 += v1.y * w;
    }
    acc0 *= dn; acc1 *= dn; acc2 *= dn; acc3 *= dn;
    size_t o = (size_t)n * HID + t * 4;
    *(__half2*)&g_agg1[o]     = __halves2half2(__float2half(acc0), __float2half(acc1));
    *(__half2*)&g_agg1[o + 2] = __halves2half2(__float2half(acc2), __float2half(acc3));
}

// ---------------- weight transpose (single fp16) ----------------
__global__ void k_wtrans(const float* __restrict__ W, int K, int Kpad,
                         __half* __restrict__ oh) {
    __shared__ float tile[32][33];
    int kb = blockIdx.x * 32, nb = blockIdx.y * 32;
    int tx = threadIdx.x, ty = threadIdx.y;   // 32 x 8
    #pragma unroll
    for (int i = 0; i < 4; i++) {
        int row = kb + ty + i * 8;
        tile[ty + i * 8][tx] = (row < K) ? W[(size_t)row * 512 + nb + tx] : 0.f;
    }
    __syncthreads();
    #pragma unroll
    for (int i = 0; i < 4; i++) {
        int n = nb + ty + i * 8;
        int k = kb + tx;
        oh[(size_t)n * Kpad + k] = __float2half(tile[tx][ty + i * 8]);
    }
}
__global__ void k_wtrans3(const float* __restrict__ Wa, const float* __restrict__ Wb,
                          const float* __restrict__ Wc,
                          __half* __restrict__ oha, __half* __restrict__ ohb,
                          __half* __restrict__ ohc) {
    __shared__ float tile[32][33];
    const float* W = (blockIdx.z == 0) ? Wa : (blockIdx.z == 1) ? Wb : Wc;
    __half* oh = (blockIdx.z == 0) ? oha : (blockIdx.z == 1) ? ohb : ohc;
    int kb = blockIdx.x * 32, nb = blockIdx.y * 32;
    int tx = threadIdx.x, ty = threadIdx.y;
    #pragma unroll
    for (int i = 0; i < 4; i++)
        tile[ty + i * 8][tx] = W[(size_t)(kb + ty + i * 8) * 512 + nb + tx];
    __syncthreads();
    #pragma unroll
    for (int i = 0; i < 4; i++) {
        int n = nb + ty + i * 8;
        int k = kb + tx;
        oh[(size_t)n * 512 + k] = __float2half(tile[tx][ty + i * 8]);
    }
}

__global__ void k_copyx(const float* __restrict__ x) {
    int t = blockIdx.x * blockDim.x + threadIdx.x;
    if (t < NN * FEA) {
        int n = t / FEA, f = t - n * FEA;
        int b = n / MA, j = n - b * MA;
        g_xcat[(size_t)b * KP0 + j * CAT + HID + f] = __float2half(x[t]);
    } else if (t < NN * FEA + BGR * 24) {
        int t2 = t - NN * FEA;
        int b = t2 / 24, f = t2 - b * 24;
        g_xcat[(size_t)b * KP0 + FLAT + f] = __float2half(0.f);
    }
}
__global__ void k_zero_t0f() {
    int t = blockIdx.x * blockDim.x + threadIdx.x;
    if (t < BGR * HID) g_t0f[t] = 0.f;
}
__global__ void k_fin_t0(const float* __restrict__ bias) {
    int t = blockIdx.x * blockDim.x + threadIdx.x;
    if (t >= BGR * HID) return;
    int c = t & 511;
    g_t0[t] = __float2half(lrelu(g_t0f[t] + bias[c]));
}

// ================= 128x128 mma GEMM, 3-stage cp.async, 1-pass fp16 =================
// EPI: 2 xcat-scatter fp16, 3 atomicAdd raw fp32, 4 fp16 row store (bias+lrelu).
template <int EPI>
__global__ void __launch_bounds__(256, 2)
k_mma_gemm(const __half* __restrict__ Ah, int lda,
           const __half* __restrict__ Bh, int ldb,
           const float* __restrict__ bias,
           float* __restrict__ Cf, __half* __restrict__ Ch,
           int ldc, int nch, int cper)
{
    constexpr uint32_t OFF_BH = 18432u;
    constexpr uint32_t BUFSZ  = 36864u;
    extern __shared__ char smx[];
    const uint32_t smb = smem_u32(smx);
    const int tid = threadIdx.x;
    const int wid = tid >> 5, lane = tid & 31;
    const int wm = wid & 1, wn = wid >> 1;
    const int row0 = blockIdx.y * 128, col0 = blockIdx.x * 128;
    const int c0 = blockIdx.z * cper;
    const int nc = min(nch, c0 + cper) - c0;

    const __half* pAh = Ah + (size_t)row0 * lda;
    const __half* pBh = Bh + (size_t)col0 * ldb;

    auto fill = [&](int b, int c) {
        const int kb = c * 64;
        uint32_t base = smb + b * BUFSZ;
        #pragma unroll
        for (int i = 0; i < 4; i++) {
            int idx = i * 256 + tid;
            int row = idx >> 3, seg = idx & 7;
            uint32_t d = base + (uint32_t)(row * 144 + seg * 16);
            CP16(d,          pAh + (size_t)row * lda + kb + seg * 8);
            CP16(d + OFF_BH, pBh + (size_t)row * ldb + kb + seg * 8);
        }
    };

    float acc[4][4][4];
    #pragma unroll
    for (int i = 0; i < 4; i++)
        #pragma unroll
        for (int j = 0; j < 4; j++)
            #pragma unroll
            for (int q = 0; q < 4; q++) acc[i][j][q] = 0.f;

    const int g2 = lane >> 3, rr = lane & 7;
    const uint32_t aoff = (uint32_t)((wm * 64 + (g2 & 1) * 8 + rr) * 144 + (g2 >> 1) * 16);
    const uint32_t boff = (uint32_t)((wn * 32 + (g2 >> 1) * 8 + rr) * 144 + (g2 & 1) * 16);

    fill(0, c0);
    CP_COMMIT();
    if (nc > 1) { fill(1, c0 + 1); CP_COMMIT(); }

    for (int ci = 0; ci < nc; ci++) {
        if (ci + 1 < nc) CP_WAIT1(); else CP_WAIT0();
        __syncthreads();
        if (ci + 2 < nc) { fill((ci + 2) % 3, c0 + ci + 2); CP_COMMIT(); }
        uint32_t base = smb + (uint32_t)(ci % 3) * BUFSZ;
        #pragma unroll
        for (int k16 = 0; k16 < 4; k16++) {
            uint32_t Af[4][4], Bf[2][4];
            #pragma unroll
            for (int mt = 0; mt < 4; mt++)
                ldsm4(Af[mt], base + aoff + mt * 2304 + k16 * 32);
            #pragma unroll
            for (int nt2 = 0; nt2 < 2; nt2++)
                ldsm4(Bf[nt2], base + OFF_BH + boff + nt2 * 2304 + k16 * 32);
            #pragma unroll
            for (int mt = 0; mt < 4; mt++)
                #pragma unroll
                for (int nt = 0; nt < 4; nt++)
                    mma16816(acc[mt][nt], Af[mt],
                             Bf[nt >> 1][(nt & 1) * 2], Bf[nt >> 1][(nt & 1) * 2 + 1]);
        }
        __syncthreads();
    }

    const int g = lane >> 2, t = lane & 3;
    #pragma unroll
    for (int mt = 0; mt < 4; mt++) {
        const int ra = row0 + wm * 64 + mt * 16 + g;
        const int rb = ra + 8;
        size_t oa = 0, ob = 0;
        if (EPI == 2) {
            int bg = ra / MA, j = ra - bg * MA;
            oa = (size_t)bg * KP0 + (size_t)j * CAT;
            bg = rb / MA; j = rb - bg * MA;
            ob = (size_t)bg * KP0 + (size_t)j * CAT;
        }
        #pragma unroll
        for (int nt = 0; nt < 4; nt++) {
            const int c = col0 + wn * 32 + nt * 8 + t * 2;
            float* d = acc[mt][nt];
            if (EPI == 3) {
                atomicAdd(&Cf[(size_t)ra * ldc + c],     d[0]);
                atomicAdd(&Cf[(size_t)ra * ldc + c + 1], d[1]);
                atomicAdd(&Cf[(size_t)rb * ldc + c],     d[2]);
                atomicAdd(&Cf[(size_t)rb * ldc + c + 1], d[3]);
            } else {
                float2 bv = *(const float2*)&bias[c];
                float v00 = lrelu(d[0] + bv.x), v01 = lrelu(d[1] + bv.y);
                float v10 = lrelu(d[2] + bv.x), v11 = lrelu(d[3] + bv.y);
                size_t pa = (EPI == 2) ? (oa + c) : ((size_t)ra * ldc + c);
                size_t pb = (EPI == 2) ? (ob + c) : ((size_t)rb * ldc + c);
                *(__half2*)&Ch[pa] = __halves2half2(__float2half(v00), __float2half(v01));
                *(__half2*)&Ch[pb] = __halves2half2(__float2half(v10), __float2half(v11));
            }
        }
    }
}

// ================= 64x64 mma GEMM (f1/f2), 1-pass fp16 =================
#define B64_BH 9216u
#define BUF64  18432u

template <int EPI>   // 0 fp32 out, 1 fp16 out
__global__ void __launch_bounds__(128, 4)
k_mma64(const __half* __restrict__ Ah, int lda,
        const __half* __restrict__ Bh, int ldb,
        const float* __restrict__ bias,
        float* __restrict__ Cf, __half* __restrict__ Ch,
        int ldc, int nc)
{
    extern __shared__ char smx[];
    const uint32_t smb = smem_u32(smx);
    const int tid = threadIdx.x;
    const int wid = tid >> 5, lane = tid & 31;
    const int wm = wid & 1, wn = wid >> 1;
    const int row0 = blockIdx.y * 64, col0 = blockIdx.x * 64;

    const __half* pAh = Ah + (size_t)row0 * lda;
    const __half* pBh = Bh + (size_t)col0 * ldb;

    auto fill = [&](int b, int c) {
        const int kb = c * 64;
        uint32_t base = smb + b * BUF64;
        #pragma unroll
        for (int i = 0; i < 4; i++) {
            int idx = i * 128 + tid;
            int row = idx >> 3, seg = idx & 7;
            uint32_t d = base + (uint32_t)(row * 144 + seg * 16);
            CP16(d,          pAh + (size_t)row * lda + kb + seg * 8);
            CP16(d + B64_BH, pBh + (size_t)row * ldb + kb + seg * 8);
        }
    };

    float acc[2][4][4];
    #pragma unroll
    for (int i = 0; i < 2; i++)
        #pragma unroll
        for (int j = 0; j < 4; j++)
            #pragma unroll
            for (int q = 0; q < 4; q++) acc[i][j][q] = 0.f;

    const int g2 = lane >> 3, rr = lane & 7;
    const uint32_t aoff = (uint32_t)((wm * 32 + (g2 & 1) * 8 + rr) * 144 + (g2 >> 1) * 16);
    const uint32_t boff = (uint32_t)((wn * 32 + (g2 >> 1) * 8 + rr) * 144 + (g2 & 1) * 16);

    fill(0, 0);
    CP_COMMIT();
    if (nc > 1) { fill(1, 1); CP_COMMIT(); }

    for (int ci = 0; ci < nc; ci++) {
        if (ci + 1 < nc) CP_WAIT1(); else CP_WAIT0();
        __syncthreads();
        if (ci + 2 < nc) { fill((ci + 2) % 3, ci + 2); CP_COMMIT(); }
        uint32_t base = smb + (uint32_t)(ci % 3) * BUF64;
        #pragma unroll
        for (int k16 = 0; k16 < 4; k16++) {
            uint32_t Af[2][4], Bf[2][4];
            #pragma unroll
            for (int mt = 0; mt < 2; mt++)
                ldsm4(Af[mt], base + aoff + mt * 2304 + k16 * 32);
            #pragma unroll
            for (int nt2 = 0; nt2 < 2; nt2++)
                ldsm4(Bf[nt2], base + B64_BH + boff + nt2 * 2304 + k16 * 32);
            #pragma unroll
            for (int mt = 0; mt < 2; mt++)
                #pragma unroll
                for (int nt = 0; nt < 4; nt++)
                    mma16816(acc[mt][nt], Af[mt],
                             Bf[nt >> 1][(nt & 1) * 2], Bf[nt >> 1][(nt & 1) * 2 + 1]);
        }
        __syncthreads();
    }

    const int g = lane >> 2, t = lane & 3;
    #pragma unroll
    for (int mt = 0; mt < 2; mt++) {
        const int ra = row0 + wm * 32 + mt * 16 + g;
        const int rb = ra + 8;
        #pragma unroll
        for (int nt = 0; nt < 4; nt++) {
            const int c = col0 + wn * 32 + nt * 8 + t * 2;
            float* d = acc[mt][nt];
            float2 bv = *(const float2*)&bias[c];
            float v00 = lrelu(d[0] + bv.x), v01 = lrelu(d[1] + bv.y);
            float v10 = lrelu(d[2] + bv.x), v11 = lrelu(d[3] + bv.y);
            if (EPI == 0) {
                float2 oA = {v00, v01}, oB = {v10, v11};
                *(float2*)&Cf[(size_t)ra * ldc + c] = oA;
                *(float2*)&Cf[(size_t)rb * ldc + c] = oB;
            } else {
                *(__half2*)&Ch[(size_t)ra * ldc + c] = __halves2half2(__float2half(v00), __float2half(v01));
                *(__half2*)&Ch[(size_t)rb * ldc + c] = __halves2half2(__float2half(v10), __float2half(v11));
            }
        }
    }
}

// ---------------- final layer ----------------
__global__ void k_out(const float* __restrict__ A, const float* __restrict__ Wo,
                      const float* __restrict__ bo, float* __restrict__ out)
{
    int b = blockIdx.x;
    int w = threadIdx.x >> 5, lane = threadIdx.x & 31;
    const float* a = A + (size_t)b * HID;
    float s = 0.f;
    for (int k = lane; k < HID; k += 32)
        s += a[k] * Wo[k * OUTD + w];
    #pragma unroll
    for (int o = 16; o > 0; o >>= 1) s += __shfl_xor_sync(0xFFFFFFFFu, s, o);
    __shared__ float sl[OUTD];
    if (lane == 0) sl[w] = s + bo[w];
    __syncthreads();
    if (threadIdx.x == 0) {
        float m = sl[0];
        #pragma unroll
        for (int o = 1; o < OUTD; o++) m = fmaxf(m, sl[o]);
        float sum = 0.f;
        #pragma unroll
        for (int o = 0; o < OUTD; o++) sum += expf(sl[o] - m);
        float l = logf(sum);
        #pragma unroll
        for (int o = 0; o < OUTD; o++) out[b * OUTD + o] = sl[o] - m - l;
    }
}

// ---------------- launch ----------------
static inline int cdiv(int a, int b) { return (a + b - 1) / b; }

extern "C" void kernel_launch(void* const* d_in, const int* in_sizes, int n_in,
                              void* d_out, int out_size)
{
    const float* x   = (const float*)d_in[0];
    const void*  ei  = d_in[1];
    const float* ew  = (const float*)d_in[2];
    const float* W1  = (const float*)d_in[3];
    const float* b1  = (const float*)d_in[4];
    const float* W2  = (const float*)d_in[5];
    const float* b2  = (const float*)d_in[6];
    const float* Wf0 = (const float*)d_in[7];
    const float* bf0 = (const float*)d_in[8];
    const float* Wf1 = (const float*)d_in[9];
    const float* bf1 = (const float*)d_in[10];
    const float* Wf2 = (const float*)d_in[11];
    const float* bf2 = (const float*)d_in[12];
    const float* Wo  = (const float*)d_in[13];
    const float* bo  = (const float*)d_in[14];
    float* out = (float*)d_out;

    __half *aggx, *W1t, *W2t, *h1, *agg1, *xcat, *Wf0t, *t0, *Wf1t, *t1, *Wf2t;
    float *t0f, *t2;
    cudaGetSymbolAddress((void**)&aggx, g_aggx);
    cudaGetSymbolAddress((void**)&W1t,  g_W1t);
    cudaGetSymbolAddress((void**)&W2t,  g_W2t);
    cudaGetSymbolAddress((void**)&h1,   g_h1);
    cudaGetSymbolAddress((void**)&agg1, g_agg1);
    cudaGetSymbolAddress((void**)&xcat, g_xcat);
    cudaGetSymbolAddress((void**)&Wf0t, g_Wf0t);
    cudaGetSymbolAddress((void**)&t0,   g_t0);
    cudaGetSymbolAddress((void**)&Wf1t, g_Wf1t);
    cudaGetSymbolAddress((void**)&t1,   g_t1);
    cudaGetSymbolAddress((void**)&Wf2t, g_Wf2t);
    cudaGetSymbolAddress((void**)&t0f,  g_t0f);
    cudaGetSymbolAddress((void**)&t2,   g_t2);

    const int SMEM1  = 3 * 36864;   // 110592
    const int SMEM64 = 3 * (int)BUF64;   // 55296
    cudaFuncSetAttribute(k_mma_gemm<2>, cudaFuncAttributeMaxDynamicSharedMemorySize, SMEM1);
    cudaFuncSetAttribute(k_mma_gemm<3>, cudaFuncAttributeMaxDynamicSharedMemorySize, SMEM1);
    cudaFuncSetAttribute(k_mma_gemm<4>, cudaFuncAttributeMaxDynamicSharedMemorySize, SMEM1);
    cudaFuncSetAttribute(k_mma64<0>, cudaFuncAttributeMaxDynamicSharedMemorySize, SMEM64);
    cudaFuncSetAttribute(k_mma64<1>, cudaFuncAttributeMaxDynamicSharedMemorySize, SMEM64);

    const int TPB = 256;

    // CSR build (no deg atomics)
    k_setup<<<cdiv(NN, TPB), TPB>>>((const int*)ei);
    k_edges<<<cdiv(EE, TPB), TPB>>>(ei);
    k_scan<<<1, 1024>>>();
    k_fill<<<cdiv(EE, TPB), TPB>>>(ew);
    k_dis2<<<cdiv(NN, TPB), TPB>>>();

    // weight transposes (fp16)
    {
        dim3 blk(32, 8);
        k_wtrans<<<dim3(2, 16), blk>>>(W1, FEA, 64, W1t);
        k_wtrans<<<dim3(KP0 / 32, 16), blk>>>(Wf0, FLAT, KP0, Wf0t);
        k_wtrans3<<<dim3(16, 16, 3), blk>>>(W2, Wf1, Wf2, W2t, Wf1t, Wf2t);
    }
    k_zero_t0f<<<cdiv(BGR * HID, TPB), TPB>>>();

    // conv1 -> h1 (fp16)
    k_gather1<<<NN, 64>>>(x);
    k_mma_gemm<4><<<dim3(4, 176, 1), 256, SMEM1>>>(
        aggx, 64, W1t, 64, b1, nullptr, h1, HID, 1, 1);

    // conv2 -> xcat scatter
    k_gather2<<<NN, 128>>>();
    k_copyx<<<cdiv(NN * FEA + BGR * 24, TPB), TPB>>>(x);
    k_mma_gemm<2><<<dim3(4, 176, 1), 256, SMEM1>>>(
        agg1, HID, W2t, HID, b2, nullptr, xcat, 0, 8, 8);

    // f0: split-K=8 fp32 atomic reduce, then bias+lrelu -> fp16 t0
    k_mma_gemm<3><<<dim3(4, 8, 8), 256, SMEM1>>>(
        xcat, KP0, Wf0t, KP0, nullptr, t0f, nullptr, HID, NCH0, 25);
    k_fin_t0<<<cdiv(BGR * HID, TPB), TPB>>>(bf0);

    // f1, f2
    k_mma64<1><<<dim3(8, 16), 128, SMEM64>>>(
        t0, HID, Wf1t, HID, bf1, nullptr, t1, HID, 8);
    k_mma64<0><<<dim3(8, 16), 128, SMEM64>>>(
        t1, HID, Wf2t, HID, bf2, t2, nullptr, HID, 8);

    // output head + log_softmax
    k_out<<<BGR, 128>>>(t2, Wo, bo, out);
}